// round 10
// baseline (speedup 1.0000x reference)
#include <cuda_runtime.h>
#include <cstdint>
#include <stdint.h>
#include <math.h>

#define N 8192
#define D 128
#define TILE 128
#define NB (N / TILE)             // 64
#define NTRI (NB * (NB + 1) / 2)  // 2080 upper-tri tiles
#define NCTA 296                  // 148 SMs x 2 resident CTAs
#define LDB 144                   // padded SMEM row stride in BYTES (int8 rows)
#define WEIGHT 0.01f

// ---------------------------------------------------------------------------
// Device scratch
// ---------------------------------------------------------------------------
__device__ uint32_t g_q[N * (D / 4)];   // int8-quantized normalized rows
__device__ float    g_scale[N];         // per-row dequant scale = max|f| / 127
__device__ float    g_suffix[N];
__device__ float    g_prefix[N];
__device__ float    g_pos[N];

// ---------------------------------------------------------------------------
__device__ __forceinline__ void mma16832(int* c,
    uint32_t a0, uint32_t a1, uint32_t a2, uint32_t a3,
    uint32_t b0, uint32_t b1)
{
    asm volatile(
        "mma.sync.aligned.m16n8k32.row.col.s32.s8.s8.s32 "
        "{%0,%1,%2,%3}, {%4,%5,%6,%7}, {%8,%9}, {%0,%1,%2,%3};"
        : "+r"(c[0]), "+r"(c[1]), "+r"(c[2]), "+r"(c[3])
        : "r"(a0), "r"(a1), "r"(a2), "r"(a3), "r"(b0), "r"(b1));
}

__device__ __forceinline__ void ldsm_x4(uint32_t& r0, uint32_t& r1,
                                        uint32_t& r2, uint32_t& r3, uint32_t a) {
    asm volatile("ldmatrix.sync.aligned.m8n8.x4.shared.b16 {%0,%1,%2,%3}, [%4];"
                 : "=r"(r0), "=r"(r1), "=r"(r2), "=r"(r3) : "r"(a));
}
__device__ __forceinline__ void ldsm_x2(uint32_t& r0, uint32_t& r1, uint32_t a) {
    asm volatile("ldmatrix.sync.aligned.m8n8.x2.shared.b16 {%0,%1}, [%2];"
                 : "=r"(r0), "=r"(r1) : "r"(a));
}

__device__ __forceinline__ uint32_t smem_u32(const void* p) {
    uint32_t a;
    asm("{ .reg .u64 t; cvta.to.shared.u64 t, %1; cvt.u32.u64 %0, t; }"
        : "=r"(a) : "l"(p));
    return a;
}

#define CP_COMMIT()   asm volatile("cp.async.commit_group;" ::: "memory")
#define CP_WAIT_ALL() asm volatile("cp.async.wait_all;" ::: "memory")

// Prefetch one 128x128-int8 tile (stride LDB) + its 128 row scales.
__device__ __forceinline__ void prefetch_tile_q(uint32_t dst_s,
                                                const uint32_t* __restrict__ srcq,
                                                uint32_t dstsc_s,
                                                const float* __restrict__ srcsc,
                                                int tid) {
#pragma unroll
    for (int it = 0; it < 4; it++) {
        int idx = tid + it * 256;          // 0..1023: 16B chunks
        int row = idx >> 3;
        int ch  = idx & 7;
        uint32_t d = dst_s + (uint32_t)(row * LDB + ch * 16);
        const void* s = (const char*)srcq + row * D + ch * 16;
        asm volatile("cp.async.cg.shared.global [%0], [%1], 16;"
                     :: "r"(d), "l"(s) : "memory");
    }
    if (tid < 32) {
        uint32_t d = dstsc_s + (uint32_t)(tid * 16);
        const void* s = srcsc + tid * 4;
        asm volatile("cp.async.cg.shared.global [%0], [%1], 16;"
                     :: "r"(d), "l"(s) : "memory");
    }
}

// ---------------------------------------------------------------------------
// Kernel 1: L2-normalize rows -> per-row max-scaled int8; zero accumulators.
// ---------------------------------------------------------------------------
__global__ void normalize_kernel(const float* __restrict__ in) {
    int row  = (blockIdx.x * blockDim.x + threadIdx.x) >> 5;
    int lane = threadIdx.x & 31;
    if (row >= N) return;
    float4 v = ((const float4*)(in + (size_t)row * D))[lane];
    float ss = v.x * v.x + v.y * v.y + v.z * v.z + v.w * v.w;
#pragma unroll
    for (int o = 16; o > 0; o >>= 1) ss += __shfl_xor_sync(0xffffffffu, ss, o);
    float scale = 1.0f / fmaxf(sqrtf(ss), 1e-12f);
    float fx = v.x * scale, fy = v.y * scale, fz = v.z * scale, fw = v.w * scale;
    float m = fmaxf(fmaxf(fabsf(fx), fabsf(fy)), fmaxf(fabsf(fz), fabsf(fw)));
#pragma unroll
    for (int o = 16; o > 0; o >>= 1)
        m = fmaxf(m, __shfl_xor_sync(0xffffffffu, m, o));
    float qs = 127.0f / m;
    int q0 = __float2int_rn(fx * qs);
    int q1 = __float2int_rn(fy * qs);
    int q2 = __float2int_rn(fz * qs);
    int q3 = __float2int_rn(fw * qs);
    uint32_t packed = (uint32_t)(q0 & 0xFF) | ((uint32_t)(q1 & 0xFF) << 8) |
                      ((uint32_t)(q2 & 0xFF) << 16) | ((uint32_t)(q3 & 0xFF) << 24);
    g_q[row * 32 + lane] = packed;
    if (lane == 0) {
        g_scale[row]  = m * (1.0f / 127.0f);
        g_suffix[row] = 0.0f;
        g_prefix[row] = 0.0f;
    }
}

// ---------------------------------------------------------------------------
// Kernel 2: persistent int8 gram (IMMA), fused exp + reductions.
// SMEM: As 18432 | Bs0 18432 | Bs1 18432 | sA 512 | sB0 512 | sB1 512
//       | s_row 512 | s_col 512  = 57856 B
// ---------------------------------------------------------------------------
#define OFF_AS   0
#define OFF_BS0  18432
#define OFF_BS1  36864
#define OFF_SA   55296
#define OFF_SB0  55808
#define OFF_SB1  56320
#define OFF_SROW 56832
#define OFF_SCOL 57344
#define SMEM_BYTES 57856

__global__ __launch_bounds__(256, 2) void gram_mma_kernel() {
    extern __shared__ char smem[];
    const uint32_t sb = smem_u32(smem);
    float* sA    = (float*)(smem + OFF_SA);
    float* sB0   = (float*)(smem + OFF_SB0);
    float* sB1   = (float*)(smem + OFF_SB1);
    float* s_row = (float*)(smem + OFF_SROW);
    float* s_col = (float*)(smem + OFF_SCOL);

    const int tid  = threadIdx.x;
    const int wid  = tid >> 5;
    const int lane = tid & 31;
    const int wrow = wid >> 2;
    const int wcol = wid & 3;
    const int g    = lane >> 2;
    const int tg   = lane & 3;

    const uint32_t aoff = (uint32_t)((lane & 15) * LDB + (lane >> 4) * 16);
    const uint32_t boff = (uint32_t)((lane & 7) * LDB + ((lane >> 3) & 1) * 16);

    const int lo = (int)(((long long)blockIdx.x * NTRI) / NCTA);
    const int hi = (int)(((long long)(blockIdx.x + 1) * NTRI) / NCTA);

    int I = 0;
    while ((I + 1) * NB - (I + 1) * I / 2 <= lo) ++I;
    {
        const int J0 = I + (lo - (I * NB - I * (I - 1) / 2));
        prefetch_tile_q(sb + OFF_AS, g_q + (size_t)I * TILE * 32,
                        sb + OFF_SA, g_scale + (size_t)I * TILE, tid);
        prefetch_tile_q(sb + OFF_BS0, g_q + (size_t)J0 * TILE * 32,
                        sb + OFF_SB0, g_scale + (size_t)J0 * TILE, tid);
        CP_COMMIT();
    }

    int buf = 0;
    for (int t = lo; t < hi; ++t) {
        while ((I + 1) * NB - (I + 1) * I / 2 <= t) ++I;
        const int J = I + (t - (I * NB - I * (I - 1) / 2));

        int In = I, Jn = 0;
        const bool have_next = (t + 1 < hi);
        if (have_next) {
            while ((In + 1) * NB - (In + 1) * In / 2 <= t + 1) ++In;
            Jn = In + ((t + 1) - (In * NB - In * (In - 1) / 2));
        }

        if (tid < TILE) s_row[tid] = 0.0f;
        else            s_col[tid - TILE] = 0.0f;

        CP_WAIT_ALL();
        __syncthreads();

        if (have_next) {
            prefetch_tile_q(sb + (buf ? OFF_BS0 : OFF_BS1),
                            g_q + (size_t)Jn * TILE * 32,
                            sb + (buf ? OFF_SB0 : OFF_SB1),
                            g_scale + (size_t)Jn * TILE, tid);
            CP_COMMIT();
        }

        const uint32_t Acur = sb + OFF_AS + aoff;
        const uint32_t Bcur = sb + (buf ? OFF_BS1 : OFF_BS0) + boff;
        const float*   sBc  = buf ? sB1 : sB0;

        int acc[4][4][4];
#pragma unroll
        for (int mt = 0; mt < 4; mt++)
#pragma unroll
            for (int nt = 0; nt < 4; nt++)
#pragma unroll
                for (int e = 0; e < 4; e++) acc[mt][nt][e] = 0;

#pragma unroll
        for (int k0 = 0; k0 < D; k0 += 32) {     // k0 in bytes (=elements)
            uint32_t bfr[4][2];
            uint32_t afr[4][4];
#pragma unroll
            for (int nt = 0; nt < 4; nt++)
                ldsm_x2(bfr[nt][0], bfr[nt][1],
                        Bcur + (uint32_t)((wcol * 32 + nt * 8) * LDB + k0));
#pragma unroll
            for (int mt = 0; mt < 4; mt++)
                ldsm_x4(afr[mt][0], afr[mt][1], afr[mt][2], afr[mt][3],
                        Acur + (uint32_t)((wrow * 64 + mt * 16) * LDB + k0));
#pragma unroll
            for (int mt = 0; mt < 4; mt++)
#pragma unroll
                for (int nt = 0; nt < 4; nt++)
                    mma16832(acc[mt][nt], afr[mt][0], afr[mt][1],
                             afr[mt][2], afr[mt][3], bfr[nt][0], bfr[nt][1]);
        }

        // --- Epilogue: dequant + exp + reductions ---
        float sBv[8];
#pragma unroll
        for (int nt = 0; nt < 4; nt++) {
            sBv[nt * 2 + 0] = sBc[wcol * 32 + nt * 8 + tg * 2 + 0];
            sBv[nt * 2 + 1] = sBc[wcol * 32 + nt * 8 + tg * 2 + 1];
        }

        float csum[4][2];
#pragma unroll
        for (int nt = 0; nt < 4; nt++) { csum[nt][0] = 0.0f; csum[nt][1] = 0.0f; }

        if (J > I + 1) {
#pragma unroll
            for (int mt = 0; mt < 4; mt++) {
                const float si0 = sA[wrow * 64 + mt * 16 + g];
                const float si1 = sA[wrow * 64 + mt * 16 + g + 8];
                float rs0 = 0.0f, rs1 = 0.0f;
#pragma unroll
                for (int nt = 0; nt < 4; nt++) {
                    float e00 = __expf((float)acc[mt][nt][0] * si0 * sBv[nt * 2 + 0]);
                    float e01 = __expf((float)acc[mt][nt][1] * si0 * sBv[nt * 2 + 1]);
                    float e10 = __expf((float)acc[mt][nt][2] * si1 * sBv[nt * 2 + 0]);
                    float e11 = __expf((float)acc[mt][nt][3] * si1 * sBv[nt * 2 + 1]);
                    rs0 += e00 + e01;
                    rs1 += e10 + e11;
                    csum[nt][0] += e00 + e10;
                    csum[nt][1] += e01 + e11;
                }
                rs0 += __shfl_xor_sync(0xffffffffu, rs0, 1);
                rs0 += __shfl_xor_sync(0xffffffffu, rs0, 2);
                rs1 += __shfl_xor_sync(0xffffffffu, rs1, 1);
                rs1 += __shfl_xor_sync(0xffffffffu, rs1, 2);
                if (tg == 0) {
                    atomicAdd(&s_row[wrow * 64 + mt * 16 + g], rs0);
                    atomicAdd(&s_row[wrow * 64 + mt * 16 + g + 8], rs1);
                }
            }
        } else {
#pragma unroll
            for (int mt = 0; mt < 4; mt++) {
                const int gi0 = I * TILE + wrow * 64 + mt * 16 + g;
                const int gi1 = gi0 + 8;
                const float si0 = sA[wrow * 64 + mt * 16 + g];
                const float si1 = sA[wrow * 64 + mt * 16 + g + 8];
                float rs0 = 0.0f, rs1 = 0.0f;
#pragma unroll
                for (int nt = 0; nt < 4; nt++) {
                    const int gj0 = J * TILE + wcol * 32 + nt * 8 + tg * 2;
                    const int gj1 = gj0 + 1;
                    float f00 = (float)acc[mt][nt][0] * si0 * sBv[nt * 2 + 0];
                    float f01 = (float)acc[mt][nt][1] * si0 * sBv[nt * 2 + 1];
                    float f10 = (float)acc[mt][nt][2] * si1 * sBv[nt * 2 + 0];
                    float f11 = (float)acc[mt][nt][3] * si1 * sBv[nt * 2 + 1];
                    float e00 = (gj0 > gi0) ? __expf(f00) : 0.0f;
                    float e01 = (gj1 > gi0) ? __expf(f01) : 0.0f;
                    float e10 = (gj0 > gi1) ? __expf(f10) : 0.0f;
                    float e11 = (gj1 > gi1) ? __expf(f11) : 0.0f;
                    rs0 += e00 + e01;
                    rs1 += e10 + e11;
                    csum[nt][0] += ((gj0 >= gi0 + 2) ? e00 : 0.0f) + ((gj0 >= gi1 + 2) ? e10 : 0.0f);
                    csum[nt][1] += ((gj1 >= gi0 + 2) ? e01 : 0.0f) + ((gj1 >= gi1 + 2) ? e11 : 0.0f);
                    if (gj0 == gi0 + 1) g_pos[gi0] = f00;
                    if (gj1 == gi0 + 1) g_pos[gi0] = f01;
                    if (gj0 == gi1 + 1) g_pos[gi1] = f10;
                    if (gj1 == gi1 + 1) g_pos[gi1] = f11;
                }
                rs0 += __shfl_xor_sync(0xffffffffu, rs0, 1);
                rs0 += __shfl_xor_sync(0xffffffffu, rs0, 2);
                rs1 += __shfl_xor_sync(0xffffffffu, rs1, 1);
                rs1 += __shfl_xor_sync(0xffffffffu, rs1, 2);
                if (tg == 0) {
                    atomicAdd(&s_row[wrow * 64 + mt * 16 + g], rs0);
                    atomicAdd(&s_row[wrow * 64 + mt * 16 + g + 8], rs1);
                }
            }
        }

#pragma unroll
        for (int nt = 0; nt < 4; nt++) {
#pragma unroll
            for (int e = 0; e < 2; e++) {
                float v = csum[nt][e];
                v += __shfl_xor_sync(0xffffffffu, v, 4);
                v += __shfl_xor_sync(0xffffffffu, v, 8);
                v += __shfl_xor_sync(0xffffffffu, v, 16);
                if (g == 0) atomicAdd(&s_col[wcol * 32 + nt * 8 + tg * 2 + e], v);
            }
        }

        __syncthreads();

        if (have_next && In != I) {
            prefetch_tile_q(sb + OFF_AS, g_q + (size_t)In * TILE * 32,
                            sb + OFF_SA, g_scale + (size_t)In * TILE, tid);
            CP_COMMIT();
        }

        if (tid < TILE) atomicAdd(&g_suffix[I * TILE + tid], s_row[tid]);
        else            atomicAdd(&g_prefix[J * TILE + tid - TILE], s_col[tid - TILE]);

        buf ^= 1;
    }
}

// ---------------------------------------------------------------------------
// Kernel 3: single-block finish (1024 threads).
// ---------------------------------------------------------------------------
__global__ void finish_kernel(float* __restrict__ out) {
    __shared__ float red[32];
    int t = threadIdx.x;
    float local = 0.0f;
    for (int r = t; r < N - 1; r += 1024)
        local += __logf(g_suffix[r] + g_prefix[r + 1]) - g_pos[r];
#pragma unroll
    for (int o = 16; o > 0; o >>= 1)
        local += __shfl_xor_sync(0xffffffffu, local, o);
    if ((t & 31) == 0) red[t >> 5] = local;
    __syncthreads();
    if (t < 32) {
        float v = red[t];
#pragma unroll
        for (int o = 16; o > 0; o >>= 1)
            v += __shfl_xor_sync(0xffffffffu, v, o);
        if (t == 0) out[0] = -WEIGHT * (v / (float)N);
    }
}

// ---------------------------------------------------------------------------
extern "C" void kernel_launch(void* const* d_in, const int* in_sizes, int n_in,
                              void* d_out, int out_size) {
    const float* factor = (const float*)d_in[0];
    (void)in_sizes; (void)n_in; (void)out_size;

    static bool attr_set = false;
    if (!attr_set) {
        cudaFuncSetAttribute(gram_mma_kernel,
                             cudaFuncAttributeMaxDynamicSharedMemorySize, SMEM_BYTES);
        attr_set = true;
    }

    normalize_kernel<<<(N * 32) / 256, 256>>>(factor);
    gram_mma_kernel<<<NCTA, 256, SMEM_BYTES>>>();
    finish_kernel<<<1, 1024>>>((float*)d_out);
}

// round 11
// speedup vs baseline: 1.6766x; 1.6766x over previous
#include <cuda_runtime.h>
#include <cuda_fp16.h>
#include <cstdint>
#include <stdint.h>
#include <math.h>

#define N 8192
#define D 128
#define TILE 128
#define NB (N / TILE)             // 64
#define NTRI (NB * (NB + 1) / 2)  // 2080 upper-tri tiles
#define NCTA 296                  // 148 SMs x 2 resident CTAs
#define NTHR 512                  // 16 warps/CTA
#define LDH 136                   // padded SMEM stride, LDSM conflict-free
#define WEIGHT 0.01f

// ---------------------------------------------------------------------------
// Device scratch
// ---------------------------------------------------------------------------
__device__ __half g_fh[N * D];
__device__ float  g_suffix[N];
__device__ float  g_prefix[N];
__device__ float  g_pos[N];

// ---------------------------------------------------------------------------
__device__ __forceinline__ void mma16816(float* c,
    uint32_t a0, uint32_t a1, uint32_t a2, uint32_t a3,
    uint32_t b0, uint32_t b1)
{
    asm volatile(
        "mma.sync.aligned.m16n8k16.row.col.f32.f16.f16.f32 "
        "{%0,%1,%2,%3}, {%4,%5,%6,%7}, {%8,%9}, {%0,%1,%2,%3};"
        : "+f"(c[0]), "+f"(c[1]), "+f"(c[2]), "+f"(c[3])
        : "r"(a0), "r"(a1), "r"(a2), "r"(a3), "r"(b0), "r"(b1));
}

__device__ __forceinline__ void ldsm_x4(uint32_t& r0, uint32_t& r1,
                                        uint32_t& r2, uint32_t& r3, uint32_t a) {
    asm volatile("ldmatrix.sync.aligned.m8n8.x4.shared.b16 {%0,%1,%2,%3}, [%4];"
                 : "=r"(r0), "=r"(r1), "=r"(r2), "=r"(r3) : "r"(a));
}
__device__ __forceinline__ void ldsm_x2(uint32_t& r0, uint32_t& r1, uint32_t a) {
    asm volatile("ldmatrix.sync.aligned.m8n8.x2.shared.b16 {%0,%1}, [%2];"
                 : "=r"(r0), "=r"(r1) : "r"(a));
}

__device__ __forceinline__ uint32_t smem_u32(const void* p) {
    uint32_t a;
    asm("{ .reg .u64 t; cvta.to.shared.u64 t, %1; cvt.u32.u64 %0, t; }"
        : "=r"(a) : "l"(p));
    return a;
}

#define CP_COMMIT()   asm volatile("cp.async.commit_group;" ::: "memory")
#define CP_WAIT_ALL() asm volatile("cp.async.wait_all;" ::: "memory")

__device__ __forceinline__ void prefetch_tile(uint32_t dst_s,
                                              const __half* __restrict__ src,
                                              int tid) {
#pragma unroll
    for (int it = 0; it < 4; it++) {
        int idx = tid + it * NTHR;        // 0..2047 : 16B chunks
        int row = idx >> 4;
        int ch  = idx & 15;
        uint32_t d = dst_s + (uint32_t)(row * LDH + ch * 8) * 2u;
        const void* s = src + row * D + ch * 8;
        asm volatile("cp.async.cg.shared.global [%0], [%1], 16;"
                     :: "r"(d), "l"(s) : "memory");
    }
}

// ---------------------------------------------------------------------------
// Kernel 1: L2-normalize rows -> fp16; zero accumulators.
// ---------------------------------------------------------------------------
__global__ void normalize_kernel(const float* __restrict__ in) {
    int gw   = (blockIdx.x * blockDim.x + threadIdx.x) >> 5;
    int lane = threadIdx.x & 31;
    if (gw >= N) return;
    float4 v = ((const float4*)(in + (size_t)gw * D))[lane];
    float ss = v.x * v.x + v.y * v.y + v.z * v.z + v.w * v.w;
#pragma unroll
    for (int o = 16; o > 0; o >>= 1) ss += __shfl_xor_sync(0xffffffffu, ss, o);
    float scale = 1.0f / fmaxf(sqrtf(ss), 1e-12f);
    __half2 h0 = __floats2half2_rn(v.x * scale, v.y * scale);
    __half2 h1 = __floats2half2_rn(v.z * scale, v.w * scale);
    ((__half2*)(g_fh + (size_t)gw * D))[lane * 2 + 0] = h0;
    ((__half2*)(g_fh + (size_t)gw * D))[lane * 2 + 1] = h1;
    if (lane == 0) { g_suffix[gw] = 0.0f; g_prefix[gw] = 0.0f; }
}

// ---------------------------------------------------------------------------
// Kernel 2: persistent gram, 16 warps/CTA, 32x32 per warp (32 acc regs).
// ---------------------------------------------------------------------------
#define SMEM_BYTES (TILE * LDH * 2 + 2 * TILE * LDH * 2 + 2 * TILE * 4)

__global__ __launch_bounds__(NTHR, 2) void gram_mma_kernel() {
    extern __shared__ char smem[];
    __half* As  = (__half*)smem;
    __half* Bs0 = As + TILE * LDH;
    __half* Bs1 = Bs0 + TILE * LDH;
    float*  s_row = (float*)(Bs1 + TILE * LDH);
    float*  s_col = s_row + TILE;

    const int tid  = threadIdx.x;
    const int wid  = tid >> 5;        // 0..15
    const int lane = tid & 31;
    const int wr   = wid >> 2;        // 0..3 -> 32-row band
    const int wc   = wid & 3;         // 0..3 -> 32-col band
    const int g    = lane >> 2;       // 0..7
    const int tg   = lane & 3;        // 0..3

    const uint32_t As_s  = smem_u32(As);
    const uint32_t Bs_s0 = smem_u32(Bs0);
    const uint32_t Bs_s1 = smem_u32(Bs1);

    const uint32_t aoff = (uint32_t)((lane & 15) * LDH + (lane >> 4) * 8) * 2u;
    const uint32_t boff = (uint32_t)((lane & 7) * LDH + ((lane >> 3) & 1) * 8) * 2u;

    const int lo = (int)(((long long)blockIdx.x * NTRI) / NCTA);
    const int hi = (int)(((long long)(blockIdx.x + 1) * NTRI) / NCTA);

    int I = 0;
    while ((I + 1) * NB - (I + 1) * I / 2 <= lo) ++I;
    {
        const int J0 = I + (lo - (I * NB - I * (I - 1) / 2));
        prefetch_tile(As_s, g_fh + (size_t)I * TILE * D, tid);
        prefetch_tile(Bs_s0, g_fh + (size_t)J0 * TILE * D, tid);
        CP_COMMIT();
    }

    int buf = 0;
    for (int t = lo; t < hi; ++t) {
        while ((I + 1) * NB - (I + 1) * I / 2 <= t) ++I;
        const int J = I + (t - (I * NB - I * (I - 1) / 2));

        int In = I, Jn = 0;
        const bool have_next = (t + 1 < hi);
        if (have_next) {
            while ((In + 1) * NB - (In + 1) * In / 2 <= t + 1) ++In;
            Jn = In + ((t + 1) - (In * NB - In * (In - 1) / 2));
        }

        // Previous tile's end-sync protects staging.
        if (tid < TILE) s_row[tid] = 0.0f;
        else if (tid < 2 * TILE) s_col[tid - TILE] = 0.0f;

        CP_WAIT_ALL();
        __syncthreads();

        if (have_next) {
            prefetch_tile(buf ? Bs_s0 : Bs_s1, g_fh + (size_t)Jn * TILE * D, tid);
            CP_COMMIT();
        }

        const uint32_t Acur = As_s + aoff + (uint32_t)(wr * 32 * LDH) * 2u;
        const uint32_t Bcur = (buf ? Bs_s1 : Bs_s0) + boff + (uint32_t)(wc * 32 * LDH) * 2u;

        float acc[2][4][4];
#pragma unroll
        for (int mt = 0; mt < 2; mt++)
#pragma unroll
            for (int nt = 0; nt < 4; nt++)
#pragma unroll
                for (int e = 0; e < 4; e++) acc[mt][nt][e] = 0.0f;

#pragma unroll
        for (int k0 = 0; k0 < D; k0 += 16) {
            uint32_t bfr[4][2];
            uint32_t afr[2][4];
#pragma unroll
            for (int nt = 0; nt < 4; nt++)
                ldsm_x2(bfr[nt][0], bfr[nt][1],
                        Bcur + (uint32_t)(nt * 8 * LDH + k0) * 2u);
#pragma unroll
            for (int mt = 0; mt < 2; mt++)
                ldsm_x4(afr[mt][0], afr[mt][1], afr[mt][2], afr[mt][3],
                        Acur + (uint32_t)(mt * 16 * LDH + k0) * 2u);
#pragma unroll
            for (int mt = 0; mt < 2; mt++)
#pragma unroll
                for (int nt = 0; nt < 4; nt++)
                    mma16816(acc[mt][nt], afr[mt][0], afr[mt][1],
                             afr[mt][2], afr[mt][3], bfr[nt][0], bfr[nt][1]);
        }

        // --- Epilogue ---
        float csum[4][2];
#pragma unroll
        for (int nt = 0; nt < 4; nt++) { csum[nt][0] = 0.0f; csum[nt][1] = 0.0f; }

        if (J > I + 1) {
#pragma unroll
            for (int mt = 0; mt < 2; mt++) {
                float rs0 = 0.0f, rs1 = 0.0f;
#pragma unroll
                for (int nt = 0; nt < 4; nt++) {
                    float e00 = __expf(acc[mt][nt][0]);
                    float e01 = __expf(acc[mt][nt][1]);
                    float e10 = __expf(acc[mt][nt][2]);
                    float e11 = __expf(acc[mt][nt][3]);
                    rs0 += e00 + e01;
                    rs1 += e10 + e11;
                    csum[nt][0] += e00 + e10;
                    csum[nt][1] += e01 + e11;
                }
                rs0 += __shfl_xor_sync(0xffffffffu, rs0, 1);
                rs0 += __shfl_xor_sync(0xffffffffu, rs0, 2);
                rs1 += __shfl_xor_sync(0xffffffffu, rs1, 1);
                rs1 += __shfl_xor_sync(0xffffffffu, rs1, 2);
                if (tg == 0) {
                    atomicAdd(&s_row[wr * 32 + mt * 16 + g], rs0);
                    atomicAdd(&s_row[wr * 32 + mt * 16 + g + 8], rs1);
                }
            }
        } else {
#pragma unroll
            for (int mt = 0; mt < 2; mt++) {
                const int gi0 = I * TILE + wr * 32 + mt * 16 + g;
                const int gi1 = gi0 + 8;
                float rs0 = 0.0f, rs1 = 0.0f;
#pragma unroll
                for (int nt = 0; nt < 4; nt++) {
                    const int gj0 = J * TILE + wc * 32 + nt * 8 + tg * 2;
                    const int gj1 = gj0 + 1;
                    float e00 = (gj0 > gi0) ? __expf(acc[mt][nt][0]) : 0.0f;
                    float e01 = (gj1 > gi0) ? __expf(acc[mt][nt][1]) : 0.0f;
                    float e10 = (gj0 > gi1) ? __expf(acc[mt][nt][2]) : 0.0f;
                    float e11 = (gj1 > gi1) ? __expf(acc[mt][nt][3]) : 0.0f;
                    rs0 += e00 + e01;
                    rs1 += e10 + e11;
                    csum[nt][0] += ((gj0 >= gi0 + 2) ? e00 : 0.0f) + ((gj0 >= gi1 + 2) ? e10 : 0.0f);
                    csum[nt][1] += ((gj1 >= gi0 + 2) ? e01 : 0.0f) + ((gj1 >= gi1 + 2) ? e11 : 0.0f);
                    if (gj0 == gi0 + 1) g_pos[gi0] = acc[mt][nt][0];
                    if (gj1 == gi0 + 1) g_pos[gi0] = acc[mt][nt][1];
                    if (gj0 == gi1 + 1) g_pos[gi1] = acc[mt][nt][2];
                    if (gj1 == gi1 + 1) g_pos[gi1] = acc[mt][nt][3];
                }
                rs0 += __shfl_xor_sync(0xffffffffu, rs0, 1);
                rs0 += __shfl_xor_sync(0xffffffffu, rs0, 2);
                rs1 += __shfl_xor_sync(0xffffffffu, rs1, 1);
                rs1 += __shfl_xor_sync(0xffffffffu, rs1, 2);
                if (tg == 0) {
                    atomicAdd(&s_row[wr * 32 + mt * 16 + g], rs0);
                    atomicAdd(&s_row[wr * 32 + mt * 16 + g + 8], rs1);
                }
            }
        }

#pragma unroll
        for (int nt = 0; nt < 4; nt++) {
#pragma unroll
            for (int e = 0; e < 2; e++) {
                float v = csum[nt][e];
                v += __shfl_xor_sync(0xffffffffu, v, 4);
                v += __shfl_xor_sync(0xffffffffu, v, 8);
                v += __shfl_xor_sync(0xffffffffu, v, 16);
                if (g == 0) atomicAdd(&s_col[wc * 32 + nt * 8 + tg * 2 + e], v);
            }
        }

        __syncthreads();

        if (have_next && In != I) {
            prefetch_tile(As_s, g_fh + (size_t)In * TILE * D, tid);
            CP_COMMIT();
        }

        if (tid < TILE) atomicAdd(&g_suffix[I * TILE + tid], s_row[tid]);
        else if (tid < 2 * TILE) atomicAdd(&g_prefix[J * TILE + tid - TILE], s_col[tid - TILE]);

        buf ^= 1;
    }
}

// ---------------------------------------------------------------------------
// Kernel 3: single-block finish (1024 threads).
// ---------------------------------------------------------------------------
__global__ void finish_kernel(float* __restrict__ out) {
    __shared__ float red[32];
    int t = threadIdx.x;
    float local = 0.0f;
    for (int r = t; r < N - 1; r += 1024)
        local += __logf(g_suffix[r] + g_prefix[r + 1]) - g_pos[r];
#pragma unroll
    for (int o = 16; o > 0; o >>= 1)
        local += __shfl_xor_sync(0xffffffffu, local, o);
    if ((t & 31) == 0) red[t >> 5] = local;
    __syncthreads();
    if (t < 32) {
        float v = red[t];
#pragma unroll
        for (int o = 16; o > 0; o >>= 1)
            v += __shfl_xor_sync(0xffffffffu, v, o);
        if (t == 0) out[0] = -WEIGHT * (v / (float)N);
    }
}

// ---------------------------------------------------------------------------
extern "C" void kernel_launch(void* const* d_in, const int* in_sizes, int n_in,
                              void* d_out, int out_size) {
    const float* factor = (const float*)d_in[0];
    (void)in_sizes; (void)n_in; (void)out_size;

    static bool attr_set = false;
    if (!attr_set) {
        cudaFuncSetAttribute(gram_mma_kernel,
                             cudaFuncAttributeMaxDynamicSharedMemorySize, SMEM_BYTES);
        attr_set = true;
    }

    normalize_kernel<<<(N * 32) / 256, 256>>>(factor);
    gram_mma_kernel<<<NCTA, NTHR, SMEM_BYTES>>>();
    finish_kernel<<<1, 1024>>>((float*)d_out);
}

// round 12
// speedup vs baseline: 1.8584x; 1.1084x over previous
#include <cuda_runtime.h>
#include <cuda_fp16.h>
#include <cstdint>
#include <stdint.h>
#include <math.h>

#define N 8192
#define D 128
#define TILE 128
#define NB (N / TILE)             // 64
#define NTRI (NB * (NB + 1) / 2)  // 2080 upper-tri tiles
#define NCTA 296                  // 148 SMs x 2 resident CTAs
#define LDH 136                   // padded SMEM stride, LDSM conflict-free
#define WEIGHT 0.01f
#define SQRT_LOG2E 1.2011224087864498f   // sqrt(log2(e))
#define LN2 0.6931471805599453f

// ---------------------------------------------------------------------------
// Device scratch
// ---------------------------------------------------------------------------
__device__ __half g_fh[N * D];    // normalized rows scaled by sqrt(log2 e)
__device__ float  g_suffix[N];
__device__ float  g_prefix[N];
__device__ float  g_pos[N];       // pos in log2 units (acc); finish x ln2

// ---------------------------------------------------------------------------
__device__ __forceinline__ void mma16816(float* c,
    uint32_t a0, uint32_t a1, uint32_t a2, uint32_t a3,
    uint32_t b0, uint32_t b1)
{
    asm volatile(
        "mma.sync.aligned.m16n8k16.row.col.f32.f16.f16.f32 "
        "{%0,%1,%2,%3}, {%4,%5,%6,%7}, {%8,%9}, {%0,%1,%2,%3};"
        : "+f"(c[0]), "+f"(c[1]), "+f"(c[2]), "+f"(c[3])
        : "r"(a0), "r"(a1), "r"(a2), "r"(a3), "r"(b0), "r"(b1));
}

__device__ __forceinline__ void ldsm_x4(uint32_t& r0, uint32_t& r1,
                                        uint32_t& r2, uint32_t& r3, uint32_t a) {
    asm volatile("ldmatrix.sync.aligned.m8n8.x4.shared.b16 {%0,%1,%2,%3}, [%4];"
                 : "=r"(r0), "=r"(r1), "=r"(r2), "=r"(r3) : "r"(a));
}
__device__ __forceinline__ void ldsm_x2(uint32_t& r0, uint32_t& r1, uint32_t a) {
    asm volatile("ldmatrix.sync.aligned.m8n8.x2.shared.b16 {%0,%1}, [%2];"
                 : "=r"(r0), "=r"(r1) : "r"(a));
}

// exp2 on MUFU, no pre-multiply (inputs already in log2 units)
__device__ __forceinline__ float ex2f(float x) {
    float y;
    asm("ex2.approx.f32 %0, %1;" : "=f"(y) : "f"(x));
    return y;
}

__device__ __forceinline__ uint32_t smem_u32(const void* p) {
    uint32_t a;
    asm("{ .reg .u64 t; cvta.to.shared.u64 t, %1; cvt.u32.u64 %0, t; }"
        : "=r"(a) : "l"(p));
    return a;
}

#define CP_COMMIT()   asm volatile("cp.async.commit_group;" ::: "memory")
#define CP_WAIT_ALL() asm volatile("cp.async.wait_all;" ::: "memory")

__device__ __forceinline__ void prefetch_tile(uint32_t dst_s,
                                              const __half* __restrict__ src,
                                              int tid) {
#pragma unroll
    for (int it = 0; it < 8; it++) {
        int idx = tid + it * 256;
        int row = idx >> 4;
        int ch  = idx & 15;
        uint32_t d = dst_s + (uint32_t)(row * LDH + ch * 8) * 2u;
        const void* s = src + row * D + ch * 8;
        asm volatile("cp.async.cg.shared.global [%0], [%1], 16;"
                     :: "r"(d), "l"(s) : "memory");
    }
}

// ---------------------------------------------------------------------------
// Kernel 1: L2-normalize rows (x sqrt(log2 e)) -> fp16; zero accumulators.
// ---------------------------------------------------------------------------
__global__ void normalize_kernel(const float* __restrict__ in) {
    int gw   = (blockIdx.x * blockDim.x + threadIdx.x) >> 5;
    int lane = threadIdx.x & 31;
    if (gw >= N) return;
    float4 v = ((const float4*)(in + (size_t)gw * D))[lane];
    float ss = v.x * v.x + v.y * v.y + v.z * v.z + v.w * v.w;
#pragma unroll
    for (int o = 16; o > 0; o >>= 1) ss += __shfl_xor_sync(0xffffffffu, ss, o);
    float scale = SQRT_LOG2E / fmaxf(sqrtf(ss), 1e-12f);
    __half2 h0 = __floats2half2_rn(v.x * scale, v.y * scale);
    __half2 h1 = __floats2half2_rn(v.z * scale, v.w * scale);
    ((__half2*)(g_fh + (size_t)gw * D))[lane * 2 + 0] = h0;
    ((__half2*)(g_fh + (size_t)gw * D))[lane * 2 + 1] = h1;
    if (lane == 0) { g_suffix[gw] = 0.0f; g_prefix[gw] = 0.0f; }
}

// ---------------------------------------------------------------------------
// Kernel 2: persistent gram; acc is sim in log2 units -> ex2 directly.
// ---------------------------------------------------------------------------
#define SMEM_BYTES (TILE * LDH * 2 + 2 * TILE * LDH * 2 + 2 * TILE * 4)

__global__ __launch_bounds__(256, 2) void gram_mma_kernel() {
    extern __shared__ char smem[];
    __half* As  = (__half*)smem;
    __half* Bs0 = As + TILE * LDH;
    __half* Bs1 = Bs0 + TILE * LDH;
    float*  s_row = (float*)(Bs1 + TILE * LDH);
    float*  s_col = s_row + TILE;

    const int tid  = threadIdx.x;
    const int wid  = tid >> 5;
    const int lane = tid & 31;
    const int wrow = wid >> 2;
    const int wcol = wid & 3;
    const int g    = lane >> 2;
    const int tg   = lane & 3;

    const uint32_t As_s  = smem_u32(As);
    const uint32_t Bs_s0 = smem_u32(Bs0);
    const uint32_t Bs_s1 = smem_u32(Bs1);

    const uint32_t aoff = (uint32_t)((lane & 15) * LDH + (lane >> 4) * 8) * 2u;
    const uint32_t boff = (uint32_t)((lane & 7) * LDH + ((lane >> 3) & 1) * 8) * 2u;

    const int lo = (int)(((long long)blockIdx.x * NTRI) / NCTA);
    const int hi = (int)(((long long)(blockIdx.x + 1) * NTRI) / NCTA);

    int I = 0;
    while ((I + 1) * NB - (I + 1) * I / 2 <= lo) ++I;
    {
        const int J0 = I + (lo - (I * NB - I * (I - 1) / 2));
        prefetch_tile(As_s, g_fh + (size_t)I * TILE * D, tid);
        prefetch_tile(Bs_s0, g_fh + (size_t)J0 * TILE * D, tid);
        CP_COMMIT();
    }

    int buf = 0;
    for (int t = lo; t < hi; ++t) {
        while ((I + 1) * NB - (I + 1) * I / 2 <= t) ++I;
        const int J = I + (t - (I * NB - I * (I - 1) / 2));

        int In = I, Jn = 0;
        const bool have_next = (t + 1 < hi);
        if (have_next) {
            while ((In + 1) * NB - (In + 1) * In / 2 <= t + 1) ++In;
            Jn = In + ((t + 1) - (In * NB - In * (In - 1) / 2));
        }

        if (tid < TILE) s_row[tid] = 0.0f;
        else            s_col[tid - TILE] = 0.0f;

        CP_WAIT_ALL();
        __syncthreads();

        if (have_next) {
            prefetch_tile(buf ? Bs_s0 : Bs_s1, g_fh + (size_t)Jn * TILE * D, tid);
            CP_COMMIT();
        }

        const uint32_t Acur = As_s + aoff;
        const uint32_t Bcur = (buf ? Bs_s1 : Bs_s0) + boff;

        float acc[4][4][4];
#pragma unroll
        for (int mt = 0; mt < 4; mt++)
#pragma unroll
            for (int nt = 0; nt < 4; nt++)
#pragma unroll
                for (int e = 0; e < 4; e++) acc[mt][nt][e] = 0.0f;

#pragma unroll
        for (int k0 = 0; k0 < D; k0 += 16) {
            uint32_t bfr[4][2];
            uint32_t afr[4][4];
#pragma unroll
            for (int nt = 0; nt < 4; nt++)
                ldsm_x2(bfr[nt][0], bfr[nt][1],
                        Bcur + (uint32_t)((wcol * 32 + nt * 8) * LDH + k0) * 2u);
#pragma unroll
            for (int mt = 0; mt < 4; mt++)
                ldsm_x4(afr[mt][0], afr[mt][1], afr[mt][2], afr[mt][3],
                        Acur + (uint32_t)((wrow * 64 + mt * 16) * LDH + k0) * 2u);
#pragma unroll
            for (int mt = 0; mt < 4; mt++)
#pragma unroll
                for (int nt = 0; nt < 4; nt++)
                    mma16816(acc[mt][nt], afr[mt][0], afr[mt][1],
                             afr[mt][2], afr[mt][3], bfr[nt][0], bfr[nt][1]);
        }

        // --- Epilogue: ex2 (no scale FMUL) + reductions ---
        float csum[4][2];
#pragma unroll
        for (int nt = 0; nt < 4; nt++) { csum[nt][0] = 0.0f; csum[nt][1] = 0.0f; }

        if (J > I + 1) {
#pragma unroll
            for (int mt = 0; mt < 4; mt++) {
                float rs0 = 0.0f, rs1 = 0.0f;
#pragma unroll
                for (int nt = 0; nt < 4; nt++) {
                    float e00 = ex2f(acc[mt][nt][0]);
                    float e01 = ex2f(acc[mt][nt][1]);
                    float e10 = ex2f(acc[mt][nt][2]);
                    float e11 = ex2f(acc[mt][nt][3]);
                    rs0 += e00 + e01;
                    rs1 += e10 + e11;
                    csum[nt][0] += e00 + e10;
                    csum[nt][1] += e01 + e11;
                }
                rs0 += __shfl_xor_sync(0xffffffffu, rs0, 1);
                rs0 += __shfl_xor_sync(0xffffffffu, rs0, 2);
                rs1 += __shfl_xor_sync(0xffffffffu, rs1, 1);
                rs1 += __shfl_xor_sync(0xffffffffu, rs1, 2);
                if (tg == 0) {
                    atomicAdd(&s_row[wrow * 64 + mt * 16 + g], rs0);
                    atomicAdd(&s_row[wrow * 64 + mt * 16 + g + 8], rs1);
                }
            }
        } else {
#pragma unroll
            for (int mt = 0; mt < 4; mt++) {
                const int gi0 = I * TILE + wrow * 64 + mt * 16 + g;
                const int gi1 = gi0 + 8;
                float rs0 = 0.0f, rs1 = 0.0f;
#pragma unroll
                for (int nt = 0; nt < 4; nt++) {
                    const int gj0 = J * TILE + wcol * 32 + nt * 8 + tg * 2;
                    const int gj1 = gj0 + 1;
                    float e00 = (gj0 > gi0) ? ex2f(acc[mt][nt][0]) : 0.0f;
                    float e01 = (gj1 > gi0) ? ex2f(acc[mt][nt][1]) : 0.0f;
                    float e10 = (gj0 > gi1) ? ex2f(acc[mt][nt][2]) : 0.0f;
                    float e11 = (gj1 > gi1) ? ex2f(acc[mt][nt][3]) : 0.0f;
                    rs0 += e00 + e01;
                    rs1 += e10 + e11;
                    csum[nt][0] += ((gj0 >= gi0 + 2) ? e00 : 0.0f) + ((gj0 >= gi1 + 2) ? e10 : 0.0f);
                    csum[nt][1] += ((gj1 >= gi0 + 2) ? e01 : 0.0f) + ((gj1 >= gi1 + 2) ? e11 : 0.0f);
                    if (gj0 == gi0 + 1) g_pos[gi0] = acc[mt][nt][0];
                    if (gj1 == gi0 + 1) g_pos[gi0] = acc[mt][nt][1];
                    if (gj0 == gi1 + 1) g_pos[gi1] = acc[mt][nt][2];
                    if (gj1 == gi1 + 1) g_pos[gi1] = acc[mt][nt][3];
                }
                rs0 += __shfl_xor_sync(0xffffffffu, rs0, 1);
                rs0 += __shfl_xor_sync(0xffffffffu, rs0, 2);
                rs1 += __shfl_xor_sync(0xffffffffu, rs1, 1);
                rs1 += __shfl_xor_sync(0xffffffffu, rs1, 2);
                if (tg == 0) {
                    atomicAdd(&s_row[wrow * 64 + mt * 16 + g], rs0);
                    atomicAdd(&s_row[wrow * 64 + mt * 16 + g + 8], rs1);
                }
            }
        }

#pragma unroll
        for (int nt = 0; nt < 4; nt++) {
#pragma unroll
            for (int e = 0; e < 2; e++) {
                float v = csum[nt][e];
                v += __shfl_xor_sync(0xffffffffu, v, 4);
                v += __shfl_xor_sync(0xffffffffu, v, 8);
                v += __shfl_xor_sync(0xffffffffu, v, 16);
                if (g == 0) atomicAdd(&s_col[wcol * 32 + nt * 8 + tg * 2 + e], v);
            }
        }

        __syncthreads();

        if (have_next && In != I) {
            prefetch_tile(As_s, g_fh + (size_t)In * TILE * D, tid);
            CP_COMMIT();
        }

        if (tid < TILE) atomicAdd(&g_suffix[I * TILE + tid], s_row[tid]);
        else            atomicAdd(&g_prefix[J * TILE + tid - TILE], s_col[tid - TILE]);

        buf ^= 1;
    }
}

// ---------------------------------------------------------------------------
// Kernel 3: single-block finish (1024 threads): lse (natural log) - pos*ln2.
// ---------------------------------------------------------------------------
__global__ void finish_kernel(float* __restrict__ out) {
    __shared__ float red[32];
    int t = threadIdx.x;
    float local = 0.0f;
    for (int r = t; r < N - 1; r += 1024)
        local += __logf(g_suffix[r] + g_prefix[r + 1]) - g_pos[r] * LN2;
#pragma unroll
    for (int o = 16; o > 0; o >>= 1)
        local += __shfl_xor_sync(0xffffffffu, local, o);
    if ((t & 31) == 0) red[t >> 5] = local;
    __syncthreads();
    if (t < 32) {
        float v = red[t];
#pragma unroll
        for (int o = 16; o > 0; o >>= 1)
            v += __shfl_xor_sync(0xffffffffu, v, o);
        if (t == 0) out[0] = -WEIGHT * (v / (float)N);
    }
}

// ---------------------------------------------------------------------------
extern "C" void kernel_launch(void* const* d_in, const int* in_sizes, int n_in,
                              void* d_out, int out_size) {
    const float* factor = (const float*)d_in[0];
    (void)in_sizes; (void)n_in; (void)out_size;

    static bool attr_set = false;
    if (!attr_set) {
        cudaFuncSetAttribute(gram_mma_kernel,
                             cudaFuncAttributeMaxDynamicSharedMemorySize, SMEM_BYTES);
        attr_set = true;
    }

    normalize_kernel<<<(N * 32) / 256, 256>>>(factor);
    gram_mma_kernel<<<NCTA, 256, SMEM_BYTES>>>();
    finish_kernel<<<1, 1024>>>((float*)d_out);
}

// round 13
// speedup vs baseline: 2.0109x; 1.0821x over previous
#include <cuda_runtime.h>
#include <cuda_fp16.h>
#include <cstdint>
#include <stdint.h>
#include <math.h>

#define N 8192
#define D 128
#define TILE 128
#define NB (N / TILE)             // 64
#define NTRI (NB * (NB + 1) / 2)  // 2080 upper-tri tiles
#define NCTA 296                  // 148 SMs x 2 resident CTAs
#define LDH 136                   // padded SMEM stride, LDSM conflict-free
#define WEIGHT 0.01f
#define SQRT_LOG2E 1.2011224087864498f
#define LN2 0.6931471805599453f

// ---------------------------------------------------------------------------
// Device scratch
// ---------------------------------------------------------------------------
__device__ __half g_fh[N * D];    // normalized rows scaled by sqrt(log2 e)
__device__ float  g_suffix[N];
__device__ float  g_prefix[N];
__device__ float  g_pos[N];       // pos in log2 units

// ---------------------------------------------------------------------------
__device__ __forceinline__ void mma16816(float* c,
    uint32_t a0, uint32_t a1, uint32_t a2, uint32_t a3,
    uint32_t b0, uint32_t b1)
{
    asm volatile(
        "mma.sync.aligned.m16n8k16.row.col.f32.f16.f16.f32 "
        "{%0,%1,%2,%3}, {%4,%5,%6,%7}, {%8,%9}, {%0,%1,%2,%3};"
        : "+f"(c[0]), "+f"(c[1]), "+f"(c[2]), "+f"(c[3])
        : "r"(a0), "r"(a1), "r"(a2), "r"(a3), "r"(b0), "r"(b1));
}

__device__ __forceinline__ void ldsm_x4(uint32_t& r0, uint32_t& r1,
                                        uint32_t& r2, uint32_t& r3, uint32_t a) {
    asm volatile("ldmatrix.sync.aligned.m8n8.x4.shared.b16 {%0,%1,%2,%3}, [%4];"
                 : "=r"(r0), "=r"(r1), "=r"(r2), "=r"(r3) : "r"(a));
}
__device__ __forceinline__ void ldsm_x2(uint32_t& r0, uint32_t& r1, uint32_t a) {
    asm volatile("ldmatrix.sync.aligned.m8n8.x2.shared.b16 {%0,%1}, [%2];"
                 : "=r"(r0), "=r"(r1) : "r"(a));
}

__device__ __forceinline__ float ex2f(float x) {
    float y;
    asm("ex2.approx.f32 %0, %1;" : "=f"(y) : "f"(x));
    return y;
}

__device__ __forceinline__ uint32_t smem_u32(const void* p) {
    uint32_t a;
    asm("{ .reg .u64 t; cvta.to.shared.u64 t, %1; cvt.u32.u64 %0, t; }"
        : "=r"(a) : "l"(p));
    return a;
}

#define CP_COMMIT()   asm volatile("cp.async.commit_group;" ::: "memory")
#define CP_WAIT_ALL() asm volatile("cp.async.wait_all;" ::: "memory")

__device__ __forceinline__ void prefetch_tile(uint32_t dst_s,
                                              const __half* __restrict__ src,
                                              int tid) {
#pragma unroll
    for (int it = 0; it < 8; it++) {
        int idx = tid + it * 256;
        int row = idx >> 4;
        int ch  = idx & 15;
        uint32_t d = dst_s + (uint32_t)(row * LDH + ch * 8) * 2u;
        const void* s = src + row * D + ch * 8;
        asm volatile("cp.async.cg.shared.global [%0], [%1], 16;"
                     :: "r"(d), "l"(s) : "memory");
    }
}

// ---------------------------------------------------------------------------
// Kernel 1: L2-normalize 4 rows per warp (MLP=4) -> fp16; zero accumulators.
// ---------------------------------------------------------------------------
__global__ void normalize_kernel(const float* __restrict__ in) {
    int warp = (blockIdx.x * blockDim.x + threadIdx.x) >> 5;   // 2048 warps
    int lane = threadIdx.x & 31;
    int r0 = warp * 4;
    if (r0 >= N) return;

    float4 v[4];
#pragma unroll
    for (int i = 0; i < 4; i++)
        v[i] = ((const float4*)(in + (size_t)(r0 + i) * D))[lane];

#pragma unroll
    for (int i = 0; i < 4; i++) {
        float ss = v[i].x * v[i].x + v[i].y * v[i].y +
                   v[i].z * v[i].z + v[i].w * v[i].w;
#pragma unroll
        for (int o = 16; o > 0; o >>= 1)
            ss += __shfl_xor_sync(0xffffffffu, ss, o);
        float scale = SQRT_LOG2E / fmaxf(sqrtf(ss), 1e-12f);
        __half2 h0 = __floats2half2_rn(v[i].x * scale, v[i].y * scale);
        __half2 h1 = __floats2half2_rn(v[i].z * scale, v[i].w * scale);
        ((__half2*)(g_fh + (size_t)(r0 + i) * D))[lane * 2 + 0] = h0;
        ((__half2*)(g_fh + (size_t)(r0 + i) * D))[lane * 2 + 1] = h1;
    }
    if (lane < 4) { g_suffix[r0 + lane] = 0.0f; g_prefix[r0 + lane] = 0.0f; }
}

// ---------------------------------------------------------------------------
// Kernel 2: persistent gram; ONE sync/tile; direct global REDG reductions.
// ---------------------------------------------------------------------------
#define SMEM_BYTES (3 * TILE * LDH * 2)    // As + Bs0 + Bs1 = 104448

__global__ __launch_bounds__(256, 2) void gram_mma_kernel() {
    extern __shared__ char smem[];
    __half* As  = (__half*)smem;
    __half* Bs0 = As + TILE * LDH;
    __half* Bs1 = Bs0 + TILE * LDH;

    const int tid  = threadIdx.x;
    const int wid  = tid >> 5;
    const int lane = tid & 31;
    const int wrow = wid >> 2;
    const int wcol = wid & 3;
    const int g    = lane >> 2;
    const int tg   = lane & 3;

    const uint32_t As_s  = smem_u32(As);
    const uint32_t Bs_s0 = smem_u32(Bs0);
    const uint32_t Bs_s1 = smem_u32(Bs1);

    const uint32_t aoff = (uint32_t)((lane & 15) * LDH + (lane >> 4) * 8) * 2u;
    const uint32_t boff = (uint32_t)((lane & 7) * LDH + ((lane >> 3) & 1) * 8) * 2u;

    const int lo = (int)(((long long)blockIdx.x * NTRI) / NCTA);
    const int hi = (int)(((long long)(blockIdx.x + 1) * NTRI) / NCTA);

    int I = 0;
    while ((I + 1) * NB - (I + 1) * I / 2 <= lo) ++I;
    {
        const int J0 = I + (lo - (I * NB - I * (I - 1) / 2));
        prefetch_tile(As_s, g_fh + (size_t)I * TILE * D, tid);
        prefetch_tile(Bs_s0, g_fh + (size_t)J0 * TILE * D, tid);
        CP_COMMIT();
    }

    int buf = 0;
    for (int t = lo; t < hi; ++t) {
        while ((I + 1) * NB - (I + 1) * I / 2 <= t) ++I;
        const int J = I + (t - (I * NB - I * (I - 1) / 2));

        int In = I, Jn = 0;
        const bool have_next = (t + 1 < hi);
        if (have_next) {
            while ((In + 1) * NB - (In + 1) * In / 2 <= t + 1) ++In;
            Jn = In + ((t + 1) - (In * NB - In * (In - 1) / 2));
        }

        CP_WAIT_ALL();
        __syncthreads();               // the ONE per-tile barrier

        if (have_next) {
            prefetch_tile(buf ? Bs_s0 : Bs_s1, g_fh + (size_t)Jn * TILE * D, tid);
            CP_COMMIT();
        }

        const uint32_t Acur = As_s + aoff;
        const uint32_t Bcur = (buf ? Bs_s1 : Bs_s0) + boff;

        float acc[4][4][4];
#pragma unroll
        for (int mt = 0; mt < 4; mt++)
#pragma unroll
            for (int nt = 0; nt < 4; nt++)
#pragma unroll
                for (int e = 0; e < 4; e++) acc[mt][nt][e] = 0.0f;

#pragma unroll
        for (int k0 = 0; k0 < D; k0 += 16) {
            uint32_t bfr[4][2];
            uint32_t afr[4][4];
#pragma unroll
            for (int nt = 0; nt < 4; nt++)
                ldsm_x2(bfr[nt][0], bfr[nt][1],
                        Bcur + (uint32_t)((wcol * 32 + nt * 8) * LDH + k0) * 2u);
#pragma unroll
            for (int mt = 0; mt < 4; mt++)
                ldsm_x4(afr[mt][0], afr[mt][1], afr[mt][2], afr[mt][3],
                        Acur + (uint32_t)((wrow * 64 + mt * 16) * LDH + k0) * 2u);
#pragma unroll
            for (int mt = 0; mt < 4; mt++)
#pragma unroll
                for (int nt = 0; nt < 4; nt++)
                    mma16816(acc[mt][nt], afr[mt][0], afr[mt][1],
                             afr[mt][2], afr[mt][3], bfr[nt][0], bfr[nt][1]);
        }

        // --- Epilogue: ex2 + shuffle reduces + direct global REDG ---
        float csum[4][2];
#pragma unroll
        for (int nt = 0; nt < 4; nt++) { csum[nt][0] = 0.0f; csum[nt][1] = 0.0f; }

        if (J > I + 1) {
#pragma unroll
            for (int mt = 0; mt < 4; mt++) {
                float rs0 = 0.0f, rs1 = 0.0f;
#pragma unroll
                for (int nt = 0; nt < 4; nt++) {
                    float e00 = ex2f(acc[mt][nt][0]);
                    float e01 = ex2f(acc[mt][nt][1]);
                    float e10 = ex2f(acc[mt][nt][2]);
                    float e11 = ex2f(acc[mt][nt][3]);
                    rs0 += e00 + e01;
                    rs1 += e10 + e11;
                    csum[nt][0] += e00 + e10;
                    csum[nt][1] += e01 + e11;
                }
                rs0 += __shfl_xor_sync(0xffffffffu, rs0, 1);
                rs0 += __shfl_xor_sync(0xffffffffu, rs0, 2);
                rs1 += __shfl_xor_sync(0xffffffffu, rs1, 1);
                rs1 += __shfl_xor_sync(0xffffffffu, rs1, 2);
                if (tg == 0) {
                    atomicAdd(&g_suffix[I * TILE + wrow * 64 + mt * 16 + g], rs0);
                    atomicAdd(&g_suffix[I * TILE + wrow * 64 + mt * 16 + g + 8], rs1);
                }
            }
        } else {
#pragma unroll
            for (int mt = 0; mt < 4; mt++) {
                const int gi0 = I * TILE + wrow * 64 + mt * 16 + g;
                const int gi1 = gi0 + 8;
                float rs0 = 0.0f, rs1 = 0.0f;
#pragma unroll
                for (int nt = 0; nt < 4; nt++) {
                    const int gj0 = J * TILE + wcol * 32 + nt * 8 + tg * 2;
                    const int gj1 = gj0 + 1;
                    float e00 = (gj0 > gi0) ? ex2f(acc[mt][nt][0]) : 0.0f;
                    float e01 = (gj1 > gi0) ? ex2f(acc[mt][nt][1]) : 0.0f;
                    float e10 = (gj0 > gi1) ? ex2f(acc[mt][nt][2]) : 0.0f;
                    float e11 = (gj1 > gi1) ? ex2f(acc[mt][nt][3]) : 0.0f;
                    rs0 += e00 + e01;
                    rs1 += e10 + e11;
                    csum[nt][0] += ((gj0 >= gi0 + 2) ? e00 : 0.0f) + ((gj0 >= gi1 + 2) ? e10 : 0.0f);
                    csum[nt][1] += ((gj1 >= gi0 + 2) ? e01 : 0.0f) + ((gj1 >= gi1 + 2) ? e11 : 0.0f);
                    if (gj0 == gi0 + 1) g_pos[gi0] = acc[mt][nt][0];
                    if (gj1 == gi0 + 1) g_pos[gi0] = acc[mt][nt][1];
                    if (gj0 == gi1 + 1) g_pos[gi1] = acc[mt][nt][2];
                    if (gj1 == gi1 + 1) g_pos[gi1] = acc[mt][nt][3];
                }
                rs0 += __shfl_xor_sync(0xffffffffu, rs0, 1);
                rs0 += __shfl_xor_sync(0xffffffffu, rs0, 2);
                rs1 += __shfl_xor_sync(0xffffffffu, rs1, 1);
                rs1 += __shfl_xor_sync(0xffffffffu, rs1, 2);
                if (tg == 0) {
                    atomicAdd(&g_suffix[gi0], rs0);
                    atomicAdd(&g_suffix[gi1], rs1);
                }
            }
        }

#pragma unroll
        for (int nt = 0; nt < 4; nt++) {
#pragma unroll
            for (int e = 0; e < 2; e++) {
                float v = csum[nt][e];
                v += __shfl_xor_sync(0xffffffffu, v, 4);
                v += __shfl_xor_sync(0xffffffffu, v, 8);
                v += __shfl_xor_sync(0xffffffffu, v, 16);
                if (g == 0)
                    atomicAdd(&g_prefix[J * TILE + wcol * 32 + nt * 8 + tg * 2 + e], v);
            }
        }

        // A changes next tile (rare): all warps must be done reading As.
        if (have_next && In != I) {
            __syncthreads();
            prefetch_tile(As_s, g_fh + (size_t)In * TILE * D, tid);
            CP_COMMIT();
        }

        buf ^= 1;
    }
}

// ---------------------------------------------------------------------------
// Kernel 3: single-block finish (1024 threads): log(sum) - pos*ln2.
// ---------------------------------------------------------------------------
__global__ void finish_kernel(float* __restrict__ out) {
    __shared__ float red[32];
    int t = threadIdx.x;
    float local = 0.0f;
    for (int r = t; r < N - 1; r += 1024)
        local += __logf(g_suffix[r] + g_prefix[r + 1]) - g_pos[r] * LN2;
#pragma unroll
    for (int o = 16; o > 0; o >>= 1)
        local += __shfl_xor_sync(0xffffffffu, local, o);
    if ((t & 31) == 0) red[t >> 5] = local;
    __syncthreads();
    if (t < 32) {
        float v = red[t];
#pragma unroll
        for (int o = 16; o > 0; o >>= 1)
            v += __shfl_xor_sync(0xffffffffu, v, o);
        if (t == 0) out[0] = -WEIGHT * (v / (float)N);
    }
}

// ---------------------------------------------------------------------------
extern "C" void kernel_launch(void* const* d_in, const int* in_sizes, int n_in,
                              void* d_out, int out_size) {
    const float* factor = (const float*)d_in[0];
    (void)in_sizes; (void)n_in; (void)out_size;

    static bool attr_set = false;
    if (!attr_set) {
        cudaFuncSetAttribute(gram_mma_kernel,
                             cudaFuncAttributeMaxDynamicSharedMemorySize, SMEM_BYTES);
        attr_set = true;
    }

    normalize_kernel<<<N / 4 / 8, 256>>>(factor);   // 2048 warps, 4 rows each
    gram_mma_kernel<<<NCTA, 256, SMEM_BYTES>>>();
    finish_kernel<<<1, 1024>>>((float*)d_out);
}

// round 14
// speedup vs baseline: 2.0213x; 1.0052x over previous
#include <cuda_runtime.h>
#include <cuda_fp16.h>
#include <cstdint>
#include <stdint.h>
#include <math.h>

#define N 8192
#define D 128
#define TILE 128
#define NB (N / TILE)             // 64
#define NTRI (NB * (NB + 1) / 2)  // 2080 upper-tri tiles
#define NCTA 296                  // 148 SMs x 2 resident CTAs
#define LDH 136                   // padded SMEM stride, LDSM conflict-free
#define WEIGHT 0.01f
#define SQRT_LOG2E 1.2011224087864498f
#define LN2 0.6931471805599453f

// ---------------------------------------------------------------------------
// Device scratch
// ---------------------------------------------------------------------------
__device__ __half   g_fh[N * D];
__device__ float    g_suffix[N];
__device__ float    g_prefix[N];
__device__ float    g_pos[N];
__device__ unsigned g_done;       // reset to 0 by the last CTA each call

// ---------------------------------------------------------------------------
__device__ __forceinline__ void mma16816(float* c,
    uint32_t a0, uint32_t a1, uint32_t a2, uint32_t a3,
    uint32_t b0, uint32_t b1)
{
    asm volatile(
        "mma.sync.aligned.m16n8k16.row.col.f32.f16.f16.f32 "
        "{%0,%1,%2,%3}, {%4,%5,%6,%7}, {%8,%9}, {%0,%1,%2,%3};"
        : "+f"(c[0]), "+f"(c[1]), "+f"(c[2]), "+f"(c[3])
        : "r"(a0), "r"(a1), "r"(a2), "r"(a3), "r"(b0), "r"(b1));
}

__device__ __forceinline__ void ldsm_x4(uint32_t& r0, uint32_t& r1,
                                        uint32_t& r2, uint32_t& r3, uint32_t a) {
    asm volatile("ldmatrix.sync.aligned.m8n8.x4.shared.b16 {%0,%1,%2,%3}, [%4];"
                 : "=r"(r0), "=r"(r1), "=r"(r2), "=r"(r3) : "r"(a));
}
__device__ __forceinline__ void ldsm_x2(uint32_t& r0, uint32_t& r1, uint32_t a) {
    asm volatile("ldmatrix.sync.aligned.m8n8.x2.shared.b16 {%0,%1}, [%2];"
                 : "=r"(r0), "=r"(r1) : "r"(a));
}

__device__ __forceinline__ float ex2f(float x) {
    float y;
    asm("ex2.approx.f32 %0, %1;" : "=f"(y) : "f"(x));
    return y;
}

__device__ __forceinline__ uint32_t smem_u32(const void* p) {
    uint32_t a;
    asm("{ .reg .u64 t; cvta.to.shared.u64 t, %1; cvt.u32.u64 %0, t; }"
        : "=r"(a) : "l"(p));
    return a;
}

#define CP_COMMIT()   asm volatile("cp.async.commit_group;" ::: "memory")
#define CP_WAIT_ALL() asm volatile("cp.async.wait_all;" ::: "memory")

__device__ __forceinline__ void prefetch_tile(uint32_t dst_s,
                                              const __half* __restrict__ src,
                                              int tid) {
#pragma unroll
    for (int it = 0; it < 8; it++) {
        int idx = tid + it * 256;
        int row = idx >> 4;
        int ch  = idx & 15;
        uint32_t d = dst_s + (uint32_t)(row * LDH + ch * 8) * 2u;
        const void* s = src + row * D + ch * 8;
        asm volatile("cp.async.cg.shared.global [%0], [%1], 16;"
                     :: "r"(d), "l"(s) : "memory");
    }
}

// ---------------------------------------------------------------------------
// Kernel 1: L2-normalize (x sqrt(log2 e)) -> fp16; zero accumulators.
// ---------------------------------------------------------------------------
__global__ void normalize_kernel(const float* __restrict__ in) {
    int gw   = (blockIdx.x * blockDim.x + threadIdx.x) >> 5;
    int lane = threadIdx.x & 31;
    if (gw >= N) return;
    float4 v = ((const float4*)(in + (size_t)gw * D))[lane];
    float ss = v.x * v.x + v.y * v.y + v.z * v.z + v.w * v.w;
#pragma unroll
    for (int o = 16; o > 0; o >>= 1) ss += __shfl_xor_sync(0xffffffffu, ss, o);
    float scale = SQRT_LOG2E / fmaxf(sqrtf(ss), 1e-12f);
    __half2 h0 = __floats2half2_rn(v.x * scale, v.y * scale);
    __half2 h1 = __floats2half2_rn(v.z * scale, v.w * scale);
    ((__half2*)(g_fh + (size_t)gw * D))[lane * 2 + 0] = h0;
    ((__half2*)(g_fh + (size_t)gw * D))[lane * 2 + 1] = h1;
    if (lane == 0) { g_suffix[gw] = 0.0f; g_prefix[gw] = 0.0f; }
}

// ---------------------------------------------------------------------------
// Kernel 2: persistent gram + last-CTA finish.
// ---------------------------------------------------------------------------
#define SMEM_BYTES (3 * TILE * LDH * 2)    // 104448

__global__ __launch_bounds__(256, 2) void gram_mma_kernel(float* __restrict__ out) {
    extern __shared__ char smem[];
    __half* As  = (__half*)smem;
    __half* Bs0 = As + TILE * LDH;
    __half* Bs1 = Bs0 + TILE * LDH;

    const int tid  = threadIdx.x;
    const int wid  = tid >> 5;
    const int lane = tid & 31;
    const int wrow = wid >> 2;
    const int wcol = wid & 3;
    const int g    = lane >> 2;
    const int tg   = lane & 3;

    const uint32_t As_s  = smem_u32(As);
    const uint32_t Bs_s0 = smem_u32(Bs0);
    const uint32_t Bs_s1 = smem_u32(Bs1);

    const uint32_t aoff = (uint32_t)((lane & 15) * LDH + (lane >> 4) * 8) * 2u;
    const uint32_t boff = (uint32_t)((lane & 7) * LDH + ((lane >> 3) & 1) * 8) * 2u;

    const int lo = (int)(((long long)blockIdx.x * NTRI) / NCTA);
    const int hi = (int)(((long long)(blockIdx.x + 1) * NTRI) / NCTA);

    int I = 0;
    while ((I + 1) * NB - (I + 1) * I / 2 <= lo) ++I;
    {
        const int J0 = I + (lo - (I * NB - I * (I - 1) / 2));
        prefetch_tile(As_s, g_fh + (size_t)I * TILE * D, tid);
        prefetch_tile(Bs_s0, g_fh + (size_t)J0 * TILE * D, tid);
        CP_COMMIT();
    }

    int buf = 0;
    for (int t = lo; t < hi; ++t) {
        while ((I + 1) * NB - (I + 1) * I / 2 <= t) ++I;
        const int J = I + (t - (I * NB - I * (I - 1) / 2));

        int In = I, Jn = 0;
        const bool have_next = (t + 1 < hi);
        if (have_next) {
            while ((In + 1) * NB - (In + 1) * In / 2 <= t + 1) ++In;
            Jn = In + ((t + 1) - (In * NB - In * (In - 1) / 2));
        }

        CP_WAIT_ALL();
        __syncthreads();               // per-tile barrier

        if (have_next) {
            prefetch_tile(buf ? Bs_s0 : Bs_s1, g_fh + (size_t)Jn * TILE * D, tid);
            CP_COMMIT();
        }

        const uint32_t Acur = As_s + aoff;
        const uint32_t Bcur = (buf ? Bs_s1 : Bs_s0) + boff;

        float acc[4][4][4];
#pragma unroll
        for (int mt = 0; mt < 4; mt++)
#pragma unroll
            for (int nt = 0; nt < 4; nt++)
#pragma unroll
                for (int e = 0; e < 4; e++) acc[mt][nt][e] = 0.0f;

#pragma unroll
        for (int k0 = 0; k0 < D; k0 += 16) {
            uint32_t bfr[4][2];
            uint32_t afr[4][4];
#pragma unroll
            for (int nt = 0; nt < 4; nt++)
                ldsm_x2(bfr[nt][0], bfr[nt][1],
                        Bcur + (uint32_t)((wcol * 32 + nt * 8) * LDH + k0) * 2u);
#pragma unroll
            for (int mt = 0; mt < 4; mt++)
                ldsm_x4(afr[mt][0], afr[mt][1], afr[mt][2], afr[mt][3],
                        Acur + (uint32_t)((wrow * 64 + mt * 16) * LDH + k0) * 2u);
#pragma unroll
            for (int mt = 0; mt < 4; mt++)
#pragma unroll
                for (int nt = 0; nt < 4; nt++)
                    mma16816(acc[mt][nt], afr[mt][0], afr[mt][1],
                             afr[mt][2], afr[mt][3], bfr[nt][0], bfr[nt][1]);
        }

        // A changes next tile: mainloop reads of As are done; prefetch now so
        // the cp.async lands during the epilogue below.
        if (have_next && In != I) {
            __syncthreads();
            prefetch_tile(As_s, g_fh + (size_t)In * TILE * D, tid);
            CP_COMMIT();
        }

        // --- Epilogue: ex2 + shuffle reduces + direct global REDG ---
        float csum[4][2];
#pragma unroll
        for (int nt = 0; nt < 4; nt++) { csum[nt][0] = 0.0f; csum[nt][1] = 0.0f; }

        if (J > I + 1) {
#pragma unroll
            for (int mt = 0; mt < 4; mt++) {
                float rs0 = 0.0f, rs1 = 0.0f;
#pragma unroll
                for (int nt = 0; nt < 4; nt++) {
                    float e00 = ex2f(acc[mt][nt][0]);
                    float e01 = ex2f(acc[mt][nt][1]);
                    float e10 = ex2f(acc[mt][nt][2]);
                    float e11 = ex2f(acc[mt][nt][3]);
                    rs0 += e00 + e01;
                    rs1 += e10 + e11;
                    csum[nt][0] += e00 + e10;
                    csum[nt][1] += e01 + e11;
                }
                rs0 += __shfl_xor_sync(0xffffffffu, rs0, 1);
                rs0 += __shfl_xor_sync(0xffffffffu, rs0, 2);
                rs1 += __shfl_xor_sync(0xffffffffu, rs1, 1);
                rs1 += __shfl_xor_sync(0xffffffffu, rs1, 2);
                if (tg == 0) {
                    atomicAdd(&g_suffix[I * TILE + wrow * 64 + mt * 16 + g], rs0);
                    atomicAdd(&g_suffix[I * TILE + wrow * 64 + mt * 16 + g + 8], rs1);
                }
            }
        } else {
#pragma unroll
            for (int mt = 0; mt < 4; mt++) {
                const int gi0 = I * TILE + wrow * 64 + mt * 16 + g;
                const int gi1 = gi0 + 8;
                float rs0 = 0.0f, rs1 = 0.0f;
#pragma unroll
                for (int nt = 0; nt < 4; nt++) {
                    const int gj0 = J * TILE + wcol * 32 + nt * 8 + tg * 2;
                    const int gj1 = gj0 + 1;
                    float e00 = (gj0 > gi0) ? ex2f(acc[mt][nt][0]) : 0.0f;
                    float e01 = (gj1 > gi0) ? ex2f(acc[mt][nt][1]) : 0.0f;
                    float e10 = (gj0 > gi1) ? ex2f(acc[mt][nt][2]) : 0.0f;
                    float e11 = (gj1 > gi1) ? ex2f(acc[mt][nt][3]) : 0.0f;
                    rs0 += e00 + e01;
                    rs1 += e10 + e11;
                    csum[nt][0] += ((gj0 >= gi0 + 2) ? e00 : 0.0f) + ((gj0 >= gi1 + 2) ? e10 : 0.0f);
                    csum[nt][1] += ((gj1 >= gi0 + 2) ? e01 : 0.0f) + ((gj1 >= gi1 + 2) ? e11 : 0.0f);
                    if (gj0 == gi0 + 1) g_pos[gi0] = acc[mt][nt][0];
                    if (gj1 == gi0 + 1) g_pos[gi0] = acc[mt][nt][1];
                    if (gj0 == gi1 + 1) g_pos[gi1] = acc[mt][nt][2];
                    if (gj1 == gi1 + 1) g_pos[gi1] = acc[mt][nt][3];
                }
                rs0 += __shfl_xor_sync(0xffffffffu, rs0, 1);
                rs0 += __shfl_xor_sync(0xffffffffu, rs0, 2);
                rs1 += __shfl_xor_sync(0xffffffffu, rs1, 1);
                rs1 += __shfl_xor_sync(0xffffffffu, rs1, 2);
                if (tg == 0) {
                    atomicAdd(&g_suffix[gi0], rs0);
                    atomicAdd(&g_suffix[gi1], rs1);
                }
            }
        }

#pragma unroll
        for (int nt = 0; nt < 4; nt++) {
#pragma unroll
            for (int e = 0; e < 2; e++) {
                float v = csum[nt][e];
                v += __shfl_xor_sync(0xffffffffu, v, 4);
                v += __shfl_xor_sync(0xffffffffu, v, 8);
                v += __shfl_xor_sync(0xffffffffu, v, 16);
                if (g == 0)
                    atomicAdd(&g_prefix[J * TILE + wcol * 32 + nt * 8 + tg * 2 + e], v);
            }
        }

        buf ^= 1;
    }

    // ===== Last-CTA finish =====
    __shared__ unsigned s_last;
    if (tid == 0) {
        __threadfence();
        s_last = (atomicAdd(&g_done, 1u) == NCTA - 1) ? 1u : 0u;
    }
    __syncthreads();
    if (!s_last) return;

    __threadfence();                   // acquire all other CTAs' REDG results

    float* red = (float*)smem;         // tile buffers are dead now
    float local = 0.0f;
    for (int r = tid; r < N - 1; r += 256)
        local += __logf(g_suffix[r] + g_prefix[r + 1]) - g_pos[r] * LN2;
#pragma unroll
    for (int o = 16; o > 0; o >>= 1)
        local += __shfl_xor_sync(0xffffffffu, local, o);
    if (lane == 0) red[wid] = local;
    __syncthreads();
    if (tid == 0) {
        float v = 0.0f;
#pragma unroll
        for (int w = 0; w < 8; w++) v += red[w];
        out[0] = -WEIGHT * (v / (float)N);
        g_done = 0;                    // reset for next graph replay
    }
}

// ---------------------------------------------------------------------------
extern "C" void kernel_launch(void* const* d_in, const int* in_sizes, int n_in,
                              void* d_out, int out_size) {
    const float* factor = (const float*)d_in[0];
    (void)in_sizes; (void)n_in; (void)out_size;

    static bool attr_set = false;
    if (!attr_set) {
        cudaFuncSetAttribute(gram_mma_kernel,
                             cudaFuncAttributeMaxDynamicSharedMemorySize, SMEM_BYTES);
        attr_set = true;
    }

    normalize_kernel<<<(N * 32) / 256, 256>>>(factor);
    gram_mma_kernel<<<NCTA, 256, SMEM_BYTES>>>((float*)d_out);
}

// round 15
// speedup vs baseline: 2.0802x; 1.0292x over previous
#include <cuda_runtime.h>
#include <cuda_fp16.h>
#include <cstdint>
#include <stdint.h>
#include <math.h>

#define N 8192
#define D 128
#define TILE 128
#define NB (N / TILE)             // 64
#define NTRI (NB * (NB + 1) / 2)  // 2080 upper-tri tiles
#define NCTA 296                  // 148 SMs x 2 resident CTAs
#define LDH 136                   // padded SMEM stride, LDSM conflict-free
#define WEIGHT 0.01f
#define SQRT_LOG2E 1.2011224087864498f
#define LN2 0.6931471805599453f

// ---------------------------------------------------------------------------
// Device scratch
// ---------------------------------------------------------------------------
__device__ __half   g_fh[N * D];
__device__ float    g_suffix[N];
__device__ float    g_prefix[N];
__device__ float    g_pos[N];
__device__ unsigned g_done;

// ---------------------------------------------------------------------------
// fp16-accumulate HMMA: D,C are 2x b32 regs (4 halves)
// reg0 = (row g,   cols tg*2, tg*2+1) ; reg1 = (row g+8, same cols)
// ---------------------------------------------------------------------------
__device__ __forceinline__ void mma16816_h(uint32_t* c,
    uint32_t a0, uint32_t a1, uint32_t a2, uint32_t a3,
    uint32_t b0, uint32_t b1)
{
    asm volatile(
        "mma.sync.aligned.m16n8k16.row.col.f16.f16.f16.f16 "
        "{%0,%1}, {%2,%3,%4,%5}, {%6,%7}, {%0,%1};"
        : "+r"(c[0]), "+r"(c[1])
        : "r"(a0), "r"(a1), "r"(a2), "r"(a3), "r"(b0), "r"(b1));
}

__device__ __forceinline__ void ldsm_x4(uint32_t& r0, uint32_t& r1,
                                        uint32_t& r2, uint32_t& r3, uint32_t a) {
    asm volatile("ldmatrix.sync.aligned.m8n8.x4.shared.b16 {%0,%1,%2,%3}, [%4];"
                 : "=r"(r0), "=r"(r1), "=r"(r2), "=r"(r3) : "r"(a));
}
__device__ __forceinline__ void ldsm_x2(uint32_t& r0, uint32_t& r1, uint32_t a) {
    asm volatile("ldmatrix.sync.aligned.m8n8.x2.shared.b16 {%0,%1}, [%2];"
                 : "=r"(r0), "=r"(r1) : "r"(a));
}

__device__ __forceinline__ float ex2f(float x) {
    float y;
    asm("ex2.approx.f32 %0, %1;" : "=f"(y) : "f"(x));
    return y;
}

__device__ __forceinline__ uint32_t smem_u32(const void* p) {
    uint32_t a;
    asm("{ .reg .u64 t; cvta.to.shared.u64 t, %1; cvt.u32.u64 %0, t; }"
        : "=r"(a) : "l"(p));
    return a;
}

#define CP_COMMIT()   asm volatile("cp.async.commit_group;" ::: "memory")
#define CP_WAIT_ALL() asm volatile("cp.async.wait_all;" ::: "memory")

__device__ __forceinline__ void prefetch_tile(uint32_t dst_s,
                                              const __half* __restrict__ src,
                                              int tid) {
#pragma unroll
    for (int it = 0; it < 8; it++) {
        int idx = tid + it * 256;
        int row = idx >> 4;
        int ch  = idx & 15;
        uint32_t d = dst_s + (uint32_t)(row * LDH + ch * 8) * 2u;
        const void* s = src + row * D + ch * 8;
        asm volatile("cp.async.cg.shared.global [%0], [%1], 16;"
                     :: "r"(d), "l"(s) : "memory");
    }
}

// ---------------------------------------------------------------------------
// Kernel 1: L2-normalize (x sqrt(log2 e)) -> fp16; zero accumulators.
// ---------------------------------------------------------------------------
__global__ void normalize_kernel(const float* __restrict__ in) {
    int gw   = (blockIdx.x * blockDim.x + threadIdx.x) >> 5;
    int lane = threadIdx.x & 31;
    if (gw >= N) return;
    float4 v = ((const float4*)(in + (size_t)gw * D))[lane];
    float ss = v.x * v.x + v.y * v.y + v.z * v.z + v.w * v.w;
#pragma unroll
    for (int o = 16; o > 0; o >>= 1) ss += __shfl_xor_sync(0xffffffffu, ss, o);
    float scale = SQRT_LOG2E / fmaxf(sqrtf(ss), 1e-12f);
    __half2 h0 = __floats2half2_rn(v.x * scale, v.y * scale);
    __half2 h1 = __floats2half2_rn(v.z * scale, v.w * scale);
    ((__half2*)(g_fh + (size_t)gw * D))[lane * 2 + 0] = h0;
    ((__half2*)(g_fh + (size_t)gw * D))[lane * 2 + 1] = h1;
    if (lane == 0) { g_suffix[gw] = 0.0f; g_prefix[gw] = 0.0f; }
}

// ---------------------------------------------------------------------------
// Kernel 2: persistent gram (fp16-acc HMMA) + packed epilogue + last-CTA finish.
// ---------------------------------------------------------------------------
#define SMEM_BYTES (3 * TILE * LDH * 2)    // 104448

__global__ __launch_bounds__(256, 2) void gram_mma_kernel(float* __restrict__ out) {
    extern __shared__ char smem[];
    __half* As  = (__half*)smem;
    __half* Bs0 = As + TILE * LDH;
    __half* Bs1 = Bs0 + TILE * LDH;

    const int tid  = threadIdx.x;
    const int wid  = tid >> 5;
    const int lane = tid & 31;
    const int wrow = wid >> 2;
    const int wcol = wid & 3;
    const int g    = lane >> 2;
    const int tg   = lane & 3;

    const uint32_t As_s  = smem_u32(As);
    const uint32_t Bs_s0 = smem_u32(Bs0);
    const uint32_t Bs_s1 = smem_u32(Bs1);

    const uint32_t aoff = (uint32_t)((lane & 15) * LDH + (lane >> 4) * 8) * 2u;
    const uint32_t boff = (uint32_t)((lane & 7) * LDH + ((lane >> 3) & 1) * 8) * 2u;

    const int lo = (int)(((long long)blockIdx.x * NTRI) / NCTA);
    const int hi = (int)(((long long)(blockIdx.x + 1) * NTRI) / NCTA);

    int I = 0;
    while ((I + 1) * NB - (I + 1) * I / 2 <= lo) ++I;
    {
        const int J0 = I + (lo - (I * NB - I * (I - 1) / 2));
        prefetch_tile(As_s, g_fh + (size_t)I * TILE * D, tid);
        prefetch_tile(Bs_s0, g_fh + (size_t)J0 * TILE * D, tid);
        CP_COMMIT();
    }

    int buf = 0;
    for (int t = lo; t < hi; ++t) {
        while ((I + 1) * NB - (I + 1) * I / 2 <= t) ++I;
        const int J = I + (t - (I * NB - I * (I - 1) / 2));

        int In = I, Jn = 0;
        const bool have_next = (t + 1 < hi);
        if (have_next) {
            while ((In + 1) * NB - (In + 1) * In / 2 <= t + 1) ++In;
            Jn = In + ((t + 1) - (In * NB - In * (In - 1) / 2));
        }

        CP_WAIT_ALL();
        __syncthreads();

        if (have_next) {
            prefetch_tile(buf ? Bs_s0 : Bs_s1, g_fh + (size_t)Jn * TILE * D, tid);
            CP_COMMIT();
        }

        const uint32_t Acur = As_s + aoff;
        const uint32_t Bcur = (buf ? Bs_s1 : Bs_s0) + boff;

        uint32_t acc[4][4][2];          // fp16x2 accumulators
#pragma unroll
        for (int mt = 0; mt < 4; mt++)
#pragma unroll
            for (int nt = 0; nt < 4; nt++) {
                acc[mt][nt][0] = 0u;
                acc[mt][nt][1] = 0u;
            }

#pragma unroll
        for (int k0 = 0; k0 < D; k0 += 16) {
            uint32_t bfr[4][2];
            uint32_t afr[4][4];
#pragma unroll
            for (int nt = 0; nt < 4; nt++)
                ldsm_x2(bfr[nt][0], bfr[nt][1],
                        Bcur + (uint32_t)((wcol * 32 + nt * 8) * LDH + k0) * 2u);
#pragma unroll
            for (int mt = 0; mt < 4; mt++)
                ldsm_x4(afr[mt][0], afr[mt][1], afr[mt][2], afr[mt][3],
                        Acur + (uint32_t)((wrow * 64 + mt * 16) * LDH + k0) * 2u);
#pragma unroll
            for (int mt = 0; mt < 4; mt++)
#pragma unroll
                for (int nt = 0; nt < 4; nt++)
                    mma16816_h(acc[mt][nt], afr[mt][0], afr[mt][1],
                               afr[mt][2], afr[mt][3], bfr[nt][0], bfr[nt][1]);
        }

        if (have_next && In != I) {
            __syncthreads();
            prefetch_tile(As_s, g_fh + (size_t)In * TILE * D, tid);
            CP_COMMIT();
        }

        // --- Epilogue ---
        if (J > I + 1) {
            // Fast path: packed f16x2 ex2 + hadd2.
            __half2 csp[4];
#pragma unroll
            for (int nt = 0; nt < 4; nt++) csp[nt] = __floats2half2_rn(0.f, 0.f);

#pragma unroll
            for (int mt = 0; mt < 4; mt++) {
                __half2 rs0p = __floats2half2_rn(0.f, 0.f);
                __half2 rs1p = __floats2half2_rn(0.f, 0.f);
#pragma unroll
                for (int nt = 0; nt < 4; nt++) {
                    __half2 e0 = h2exp2(*(__half2*)&acc[mt][nt][0]);
                    __half2 e1 = h2exp2(*(__half2*)&acc[mt][nt][1]);
                    rs0p = __hadd2(rs0p, e0);
                    rs1p = __hadd2(rs1p, e1);
                    csp[nt] = __hadd2(csp[nt], __hadd2(e0, e1));
                }
                float rs0 = __low2float(rs0p) + __high2float(rs0p);
                float rs1 = __low2float(rs1p) + __high2float(rs1p);
                rs0 += __shfl_xor_sync(0xffffffffu, rs0, 1);
                rs0 += __shfl_xor_sync(0xffffffffu, rs0, 2);
                rs1 += __shfl_xor_sync(0xffffffffu, rs1, 1);
                rs1 += __shfl_xor_sync(0xffffffffu, rs1, 2);
                if (tg == 0) {
                    atomicAdd(&g_suffix[I * TILE + wrow * 64 + mt * 16 + g], rs0);
                    atomicAdd(&g_suffix[I * TILE + wrow * 64 + mt * 16 + g + 8], rs1);
                }
            }
#pragma unroll
            for (int nt = 0; nt < 4; nt++) {
                float c0 = __low2float(csp[nt]);
                float c1 = __high2float(csp[nt]);
#pragma unroll
                for (int o = 4; o <= 16; o <<= 1) {
                    c0 += __shfl_xor_sync(0xffffffffu, c0, o);
                    c1 += __shfl_xor_sync(0xffffffffu, c1, o);
                }
                if (g == 0) {
                    atomicAdd(&g_prefix[J * TILE + wcol * 32 + nt * 8 + tg * 2 + 0], c0);
                    atomicAdd(&g_prefix[J * TILE + wcol * 32 + nt * 8 + tg * 2 + 1], c1);
                }
            }
        } else {
            // Masked path (127 tiles): unpack to fp32, as before.
            float csum[4][2];
#pragma unroll
            for (int nt = 0; nt < 4; nt++) { csum[nt][0] = 0.0f; csum[nt][1] = 0.0f; }
#pragma unroll
            for (int mt = 0; mt < 4; mt++) {
                const int gi0 = I * TILE + wrow * 64 + mt * 16 + g;
                const int gi1 = gi0 + 8;
                float rs0 = 0.0f, rs1 = 0.0f;
#pragma unroll
                for (int nt = 0; nt < 4; nt++) {
                    const int gj0 = J * TILE + wcol * 32 + nt * 8 + tg * 2;
                    const int gj1 = gj0 + 1;
                    float2 f0 = __half22float2(*(__half2*)&acc[mt][nt][0]);
                    float2 f1 = __half22float2(*(__half2*)&acc[mt][nt][1]);
                    float e00 = (gj0 > gi0) ? ex2f(f0.x) : 0.0f;
                    float e01 = (gj1 > gi0) ? ex2f(f0.y) : 0.0f;
                    float e10 = (gj0 > gi1) ? ex2f(f1.x) : 0.0f;
                    float e11 = (gj1 > gi1) ? ex2f(f1.y) : 0.0f;
                    rs0 += e00 + e01;
                    rs1 += e10 + e11;
                    csum[nt][0] += ((gj0 >= gi0 + 2) ? e00 : 0.0f) + ((gj0 >= gi1 + 2) ? e10 : 0.0f);
                    csum[nt][1] += ((gj1 >= gi0 + 2) ? e01 : 0.0f) + ((gj1 >= gi1 + 2) ? e11 : 0.0f);
                    if (gj0 == gi0 + 1) g_pos[gi0] = f0.x;
                    if (gj1 == gi0 + 1) g_pos[gi0] = f0.y;
                    if (gj0 == gi1 + 1) g_pos[gi1] = f1.x;
                    if (gj1 == gi1 + 1) g_pos[gi1] = f1.y;
                }
                rs0 += __shfl_xor_sync(0xffffffffu, rs0, 1);
                rs0 += __shfl_xor_sync(0xffffffffu, rs0, 2);
                rs1 += __shfl_xor_sync(0xffffffffu, rs1, 1);
                rs1 += __shfl_xor_sync(0xffffffffu, rs1, 2);
                if (tg == 0) {
                    atomicAdd(&g_suffix[gi0], rs0);
                    atomicAdd(&g_suffix[gi1], rs1);
                }
            }
#pragma unroll
            for (int nt = 0; nt < 4; nt++) {
#pragma unroll
                for (int e = 0; e < 2; e++) {
                    float v = csum[nt][e];
                    v += __shfl_xor_sync(0xffffffffu, v, 4);
                    v += __shfl_xor_sync(0xffffffffu, v, 8);
                    v += __shfl_xor_sync(0xffffffffu, v, 16);
                    if (g == 0)
                        atomicAdd(&g_prefix[J * TILE + wcol * 32 + nt * 8 + tg * 2 + e], v);
                }
            }
        }

        buf ^= 1;
    }

    // ===== Last-CTA finish =====
    __shared__ unsigned s_last;
    if (tid == 0) {
        __threadfence();
        s_last = (atomicAdd(&g_done, 1u) == NCTA - 1) ? 1u : 0u;
    }
    __syncthreads();
    if (!s_last) return;

    __threadfence();

    float* red = (float*)smem;
    float local = 0.0f;
    for (int r = tid; r < N - 1; r += 256)
        local += __logf(g_suffix[r] + g_prefix[r + 1]) - g_pos[r] * LN2;
#pragma unroll
    for (int o = 16; o > 0; o >>= 1)
        local += __shfl_xor_sync(0xffffffffu, local, o);
    if (lane == 0) red[wid] = local;
    __syncthreads();
    if (tid == 0) {
        float v = 0.0f;
#pragma unroll
        for (int w = 0; w < 8; w++) v += red[w];
        out[0] = -WEIGHT * (v / (float)N);
        g_done = 0;
    }
}

// ---------------------------------------------------------------------------
extern "C" void kernel_launch(void* const* d_in, const int* in_sizes, int n_in,
                              void* d_out, int out_size) {
    const float* factor = (const float*)d_in[0];
    (void)in_sizes; (void)n_in; (void)out_size;

    static bool attr_set = false;
    if (!attr_set) {
        cudaFuncSetAttribute(gram_mma_kernel,
                             cudaFuncAttributeMaxDynamicSharedMemorySize, SMEM_BYTES);
        attr_set = true;
    }

    normalize_kernel<<<(N * 32) / 256, 256>>>(factor);
    gram_mma_kernel<<<NCTA, 256, SMEM_BYTES>>>((float*)d_out);
}

// round 16
// speedup vs baseline: 2.2154x; 1.0650x over previous
#include <cuda_runtime.h>
#include <cuda_fp16.h>
#include <cstdint>
#include <stdint.h>
#include <math.h>

#define N 8192
#define D 128
#define TILE 128
#define NB (N / TILE)             // 64
#define NTRI (NB * (NB + 1) / 2)  // 2080 upper-tri tiles
#define NCTA 444                  // 148 SMs x 3 resident CTAs
#define LDH 136                   // padded SMEM stride, LDSM conflict-free
#define WEIGHT 0.01f
#define SQRT_LOG2E 1.2011224087864498f
#define LN2 0.6931471805599453f

// ---------------------------------------------------------------------------
// Device scratch
// ---------------------------------------------------------------------------
__device__ __half   g_fh[N * D];
__device__ float    g_suffix[N];
__device__ float    g_prefix[N];
__device__ float    g_pos[N];
__device__ unsigned g_done;

// ---------------------------------------------------------------------------
__device__ __forceinline__ void mma16816_h(uint32_t* c,
    uint32_t a0, uint32_t a1, uint32_t a2, uint32_t a3,
    uint32_t b0, uint32_t b1)
{
    asm volatile(
        "mma.sync.aligned.m16n8k16.row.col.f16.f16.f16.f16 "
        "{%0,%1}, {%2,%3,%4,%5}, {%6,%7}, {%0,%1};"
        : "+r"(c[0]), "+r"(c[1])
        : "r"(a0), "r"(a1), "r"(a2), "r"(a3), "r"(b0), "r"(b1));
}

__device__ __forceinline__ void ldsm_x4(uint32_t& r0, uint32_t& r1,
                                        uint32_t& r2, uint32_t& r3, uint32_t a) {
    asm volatile("ldmatrix.sync.aligned.m8n8.x4.shared.b16 {%0,%1,%2,%3}, [%4];"
                 : "=r"(r0), "=r"(r1), "=r"(r2), "=r"(r3) : "r"(a));
}
__device__ __forceinline__ void ldsm_x2(uint32_t& r0, uint32_t& r1, uint32_t a) {
    asm volatile("ldmatrix.sync.aligned.m8n8.x2.shared.b16 {%0,%1}, [%2];"
                 : "=r"(r0), "=r"(r1) : "r"(a));
}

__device__ __forceinline__ float ex2f(float x) {
    float y;
    asm("ex2.approx.f32 %0, %1;" : "=f"(y) : "f"(x));
    return y;
}

__device__ __forceinline__ uint32_t smem_u32(const void* p) {
    uint32_t a;
    asm("{ .reg .u64 t; cvta.to.shared.u64 t, %1; cvt.u32.u64 %0, t; }"
        : "=r"(a) : "l"(p));
    return a;
}

#define CP_COMMIT()   asm volatile("cp.async.commit_group;" ::: "memory")
#define CP_WAIT_ALL() asm volatile("cp.async.wait_all;" ::: "memory")

__device__ __forceinline__ void prefetch_tile(uint32_t dst_s,
                                              const __half* __restrict__ src,
                                              int tid) {
#pragma unroll
    for (int it = 0; it < 8; it++) {
        int idx = tid + it * 256;
        int row = idx >> 4;
        int ch  = idx & 15;
        uint32_t d = dst_s + (uint32_t)(row * LDH + ch * 8) * 2u;
        const void* s = src + row * D + ch * 8;
        asm volatile("cp.async.cg.shared.global [%0], [%1], 16;"
                     :: "r"(d), "l"(s) : "memory");
    }
}

// ---------------------------------------------------------------------------
// Kernel 1: L2-normalize (x sqrt(log2 e)) -> fp16; zero accumulators.
// ---------------------------------------------------------------------------
__global__ void normalize_kernel(const float* __restrict__ in) {
    int gw   = (blockIdx.x * blockDim.x + threadIdx.x) >> 5;
    int lane = threadIdx.x & 31;
    if (gw >= N) return;
    float4 v = ((const float4*)(in + (size_t)gw * D))[lane];
    float ss = v.x * v.x + v.y * v.y + v.z * v.z + v.w * v.w;
#pragma unroll
    for (int o = 16; o > 0; o >>= 1) ss += __shfl_xor_sync(0xffffffffu, ss, o);
    float scale = SQRT_LOG2E / fmaxf(sqrtf(ss), 1e-12f);
    __half2 h0 = __floats2half2_rn(v.x * scale, v.y * scale);
    __half2 h1 = __floats2half2_rn(v.z * scale, v.w * scale);
    ((__half2*)(g_fh + (size_t)gw * D))[lane * 2 + 0] = h0;
    ((__half2*)(g_fh + (size_t)gw * D))[lane * 2 + 1] = h1;
    if (lane == 0) { g_suffix[gw] = 0.0f; g_prefix[gw] = 0.0f; }
}

// ---------------------------------------------------------------------------
// Kernel 2: persistent gram, 3 CTAs/SM, single B buffer (prefetch behind
// epilogue), fp16-acc HMMA, packed epilogue, last-CTA finish.
// ---------------------------------------------------------------------------
#define SMEM_BYTES (2 * TILE * LDH * 2)    // As + Bs = 69632

__global__ __launch_bounds__(256, 3) void gram_mma_kernel(float* __restrict__ out) {
    extern __shared__ char smem[];
    __half* As = (__half*)smem;
    __half* Bs = As + TILE * LDH;

    const int tid  = threadIdx.x;
    const int wid  = tid >> 5;
    const int lane = tid & 31;
    const int wrow = wid >> 2;
    const int wcol = wid & 3;
    const int g    = lane >> 2;
    const int tg   = lane & 3;

    const uint32_t As_s = smem_u32(As);
    const uint32_t Bs_s = smem_u32(Bs);

    const uint32_t aoff = (uint32_t)((lane & 15) * LDH + (lane >> 4) * 8) * 2u;
    const uint32_t boff = (uint32_t)((lane & 7) * LDH + ((lane >> 3) & 1) * 8) * 2u;

    const int lo = (int)(((long long)blockIdx.x * NTRI) / NCTA);
    const int hi = (int)(((long long)(blockIdx.x + 1) * NTRI) / NCTA);

    int I = 0;
    while ((I + 1) * NB - (I + 1) * I / 2 <= lo) ++I;
    {
        const int J0 = I + (lo - (I * NB - I * (I - 1) / 2));
        prefetch_tile(As_s, g_fh + (size_t)I * TILE * D, tid);
        prefetch_tile(Bs_s, g_fh + (size_t)J0 * TILE * D, tid);
        CP_COMMIT();
    }

    for (int t = lo; t < hi; ++t) {
        while ((I + 1) * NB - (I + 1) * I / 2 <= t) ++I;
        const int J = I + (t - (I * NB - I * (I - 1) / 2));

        int In = I, Jn = 0;
        const bool have_next = (t + 1 < hi);
        if (have_next) {
            while ((In + 1) * NB - (In + 1) * In / 2 <= t + 1) ++In;
            Jn = In + ((t + 1) - (In * NB - In * (In - 1) / 2));
        }

        CP_WAIT_ALL();
        __syncthreads();               // tiles visible to all warps

        const uint32_t Acur = As_s + aoff;
        const uint32_t Bcur = Bs_s + boff;

        uint32_t acc[4][4][2];
#pragma unroll
        for (int mt = 0; mt < 4; mt++)
#pragma unroll
            for (int nt = 0; nt < 4; nt++) {
                acc[mt][nt][0] = 0u;
                acc[mt][nt][1] = 0u;
            }

#pragma unroll
        for (int k0 = 0; k0 < D; k0 += 16) {
            uint32_t bfr[4][2];
            uint32_t afr[4][4];
#pragma unroll
            for (int nt = 0; nt < 4; nt++)
                ldsm_x2(bfr[nt][0], bfr[nt][1],
                        Bcur + (uint32_t)((wcol * 32 + nt * 8) * LDH + k0) * 2u);
#pragma unroll
            for (int mt = 0; mt < 4; mt++)
                ldsm_x4(afr[mt][0], afr[mt][1], afr[mt][2], afr[mt][3],
                        Acur + (uint32_t)((wrow * 64 + mt * 16) * LDH + k0) * 2u);
#pragma unroll
            for (int mt = 0; mt < 4; mt++)
#pragma unroll
                for (int nt = 0; nt < 4; nt++)
                    mma16816_h(acc[mt][nt], afr[mt][0], afr[mt][1],
                               afr[mt][2], afr[mt][3], bfr[nt][0], bfr[nt][1]);
        }

        // All warps done reading tiles: prefetch next tiles NOW so the loads
        // land behind the epilogue below.
        __syncthreads();
        if (have_next) {
            prefetch_tile(Bs_s, g_fh + (size_t)Jn * TILE * D, tid);
            if (In != I)
                prefetch_tile(As_s, g_fh + (size_t)In * TILE * D, tid);
            CP_COMMIT();
        }

        // --- Epilogue ---
        if (J > I + 1) {
            __half2 csp[4];
#pragma unroll
            for (int nt = 0; nt < 4; nt++) csp[nt] = __floats2half2_rn(0.f, 0.f);

#pragma unroll
            for (int mt = 0; mt < 4; mt++) {
                __half2 rs0p = __floats2half2_rn(0.f, 0.f);
                __half2 rs1p = __floats2half2_rn(0.f, 0.f);
#pragma unroll
                for (int nt = 0; nt < 4; nt++) {
                    __half2 e0 = h2exp2(*(__half2*)&acc[mt][nt][0]);
                    __half2 e1 = h2exp2(*(__half2*)&acc[mt][nt][1]);
                    rs0p = __hadd2(rs0p, e0);
                    rs1p = __hadd2(rs1p, e1);
                    csp[nt] = __hadd2(csp[nt], __hadd2(e0, e1));
                }
                float rs0 = __low2float(rs0p) + __high2float(rs0p);
                float rs1 = __low2float(rs1p) + __high2float(rs1p);
                rs0 += __shfl_xor_sync(0xffffffffu, rs0, 1);
                rs0 += __shfl_xor_sync(0xffffffffu, rs0, 2);
                rs1 += __shfl_xor_sync(0xffffffffu, rs1, 1);
                rs1 += __shfl_xor_sync(0xffffffffu, rs1, 2);
                if (tg == 0) {
                    atomicAdd(&g_suffix[I * TILE + wrow * 64 + mt * 16 + g], rs0);
                    atomicAdd(&g_suffix[I * TILE + wrow * 64 + mt * 16 + g + 8], rs1);
                }
            }
#pragma unroll
            for (int nt = 0; nt < 4; nt++) {
                float c0 = __low2float(csp[nt]);
                float c1 = __high2float(csp[nt]);
#pragma unroll
                for (int o = 4; o <= 16; o <<= 1) {
                    c0 += __shfl_xor_sync(0xffffffffu, c0, o);
                    c1 += __shfl_xor_sync(0xffffffffu, c1, o);
                }
                if (g == 0) {
                    atomicAdd(&g_prefix[J * TILE + wcol * 32 + nt * 8 + tg * 2 + 0], c0);
                    atomicAdd(&g_prefix[J * TILE + wcol * 32 + nt * 8 + tg * 2 + 1], c1);
                }
            }
        } else {
            float csum[4][2];
#pragma unroll
            for (int nt = 0; nt < 4; nt++) { csum[nt][0] = 0.0f; csum[nt][1] = 0.0f; }
#pragma unroll
            for (int mt = 0; mt < 4; mt++) {
                const int gi0 = I * TILE + wrow * 64 + mt * 16 + g;
                const int gi1 = gi0 + 8;
                float rs0 = 0.0f, rs1 = 0.0f;
#pragma unroll
                for (int nt = 0; nt < 4; nt++) {
                    const int gj0 = J * TILE + wcol * 32 + nt * 8 + tg * 2;
                    const int gj1 = gj0 + 1;
                    float2 f0 = __half22float2(*(__half2*)&acc[mt][nt][0]);
                    float2 f1 = __half22float2(*(__half2*)&acc[mt][nt][1]);
                    float e00 = (gj0 > gi0) ? ex2f(f0.x) : 0.0f;
                    float e01 = (gj1 > gi0) ? ex2f(f0.y) : 0.0f;
                    float e10 = (gj0 > gi1) ? ex2f(f1.x) : 0.0f;
                    float e11 = (gj1 > gi1) ? ex2f(f1.y) : 0.0f;
                    rs0 += e00 + e01;
                    rs1 += e10 + e11;
                    csum[nt][0] += ((gj0 >= gi0 + 2) ? e00 : 0.0f) + ((gj0 >= gi1 + 2) ? e10 : 0.0f);
                    csum[nt][1] += ((gj1 >= gi0 + 2) ? e01 : 0.0f) + ((gj1 >= gi1 + 2) ? e11 : 0.0f);
                    if (gj0 == gi0 + 1) g_pos[gi0] = f0.x;
                    if (gj1 == gi0 + 1) g_pos[gi0] = f0.y;
                    if (gj0 == gi1 + 1) g_pos[gi1] = f1.x;
                    if (gj1 == gi1 + 1) g_pos[gi1] = f1.y;
                }
                rs0 += __shfl_xor_sync(0xffffffffu, rs0, 1);
                rs0 += __shfl_xor_sync(0xffffffffu, rs0, 2);
                rs1 += __shfl_xor_sync(0xffffffffu, rs1, 1);
                rs1 += __shfl_xor_sync(0xffffffffu, rs1, 2);
                if (tg == 0) {
                    atomicAdd(&g_suffix[gi0], rs0);
                    atomicAdd(&g_suffix[gi1], rs1);
                }
            }
#pragma unroll
            for (int nt = 0; nt < 4; nt++) {
#pragma unroll
                for (int e = 0; e < 2; e++) {
                    float v = csum[nt][e];
                    v += __shfl_xor_sync(0xffffffffu, v, 4);
                    v += __shfl_xor_sync(0xffffffffu, v, 8);
                    v += __shfl_xor_sync(0xffffffffu, v, 16);
                    if (g == 0)
                        atomicAdd(&g_prefix[J * TILE + wcol * 32 + nt * 8 + tg * 2 + e], v);
                }
            }
        }
    }

    // ===== Last-CTA finish =====
    __shared__ unsigned s_last;
    if (tid == 0) {
        __threadfence();
        s_last = (atomicAdd(&g_done, 1u) == NCTA - 1) ? 1u : 0u;
    }
    __syncthreads();
    if (!s_last) return;

    __threadfence();

    float* red = (float*)smem;
    float local = 0.0f;
    for (int r = tid; r < N - 1; r += 256)
        local += __logf(g_suffix[r] + g_prefix[r + 1]) - g_pos[r] * LN2;
#pragma unroll
    for (int o = 16; o > 0; o >>= 1)
        local += __shfl_xor_sync(0xffffffffu, local, o);
    if (lane == 0) red[wid] = local;
    __syncthreads();
    if (tid == 0) {
        float v = 0.0f;
#pragma unroll
        for (int w = 0; w < 8; w++) v += red[w];
        out[0] = -WEIGHT * (v / (float)N);
        g_done = 0;
    }
}

// ---------------------------------------------------------------------------
extern "C" void kernel_launch(void* const* d_in, const int* in_sizes, int n_in,
                              void* d_out, int out_size) {
    const float* factor = (const float*)d_in[0];
    (void)in_sizes; (void)n_in; (void)out_size;

    static bool attr_set = false;
    if (!attr_set) {
        cudaFuncSetAttribute(gram_mma_kernel,
                             cudaFuncAttributeMaxDynamicSharedMemorySize, SMEM_BYTES);
        attr_set = true;
    }

    normalize_kernel<<<(N * 32) / 256, 256>>>(factor);
    gram_mma_kernel<<<NCTA, 256, SMEM_BYTES>>>((float*)d_out);
}

// round 17
// speedup vs baseline: 2.2264x; 1.0050x over previous
#include <cuda_runtime.h>
#include <cuda_fp16.h>
#include <cstdint>
#include <stdint.h>
#include <math.h>

#define N 8192
#define D 128
#define TILE 128
#define NB (N / TILE)             // 64
#define NTRI (NB * (NB + 1) / 2)  // 2080
#define NCTA 444                  // 148 SMs x 3 resident CTAs (verified r16)
#define LDH 136
#define WEIGHT 0.01f
#define SQRT_LOG2E 1.2011224087864498f
#define LN2 0.6931471805599453f

// ---------------------------------------------------------------------------
__device__ __half   g_fh[N * D];
__device__ float    g_suffix[N];
__device__ float    g_prefix[N];
__device__ float    g_pos[N];
__device__ unsigned g_sync;       // normalize barrier
__device__ unsigned g_done;       // finish counter

// ---------------------------------------------------------------------------
__device__ __forceinline__ void mma16816_h(uint32_t* c,
    uint32_t a0, uint32_t a1, uint32_t a2, uint32_t a3,
    uint32_t b0, uint32_t b1)
{
    asm volatile(
        "mma.sync.aligned.m16n8k16.row.col.f16.f16.f16.f16 "
        "{%0,%1}, {%2,%3,%4,%5}, {%6,%7}, {%0,%1};"
        : "+r"(c[0]), "+r"(c[1])
        : "r"(a0), "r"(a1), "r"(a2), "r"(a3), "r"(b0), "r"(b1));
}

__device__ __forceinline__ void ldsm_x4(uint32_t& r0, uint32_t& r1,
                                        uint32_t& r2, uint32_t& r3, uint32_t a) {
    asm volatile("ldmatrix.sync.aligned.m8n8.x4.shared.b16 {%0,%1,%2,%3}, [%4];"
                 : "=r"(r0), "=r"(r1), "=r"(r2), "=r"(r3) : "r"(a));
}

__device__ __forceinline__ float ex2f(float x) {
    float y;
    asm("ex2.approx.f32 %0, %1;" : "=f"(y) : "f"(x));
    return y;
}

__device__ __forceinline__ uint32_t smem_u32(const void* p) {
    uint32_t a;
    asm("{ .reg .u64 t; cvta.to.shared.u64 t, %1; cvt.u32.u64 %0, t; }"
        : "=r"(a) : "l"(p));
    return a;
}

#define CP_COMMIT()   asm volatile("cp.async.commit_group;" ::: "memory")
#define CP_WAIT_ALL() asm volatile("cp.async.wait_all;" ::: "memory")

__device__ __forceinline__ void prefetch_tile(uint32_t dst_s,
                                              const __half* __restrict__ src,
                                              int tid) {
#pragma unroll
    for (int it = 0; it < 8; it++) {
        int idx = tid + it * 256;
        int row = idx >> 4;
        int ch  = idx & 15;
        uint32_t d = dst_s + (uint32_t)(row * LDH + ch * 8) * 2u;
        const void* s = src + row * D + ch * 8;
        asm volatile("cp.async.cg.shared.global [%0], [%1], 16;"
                     :: "r"(d), "l"(s) : "memory");
    }
}

// ---------------------------------------------------------------------------
// Single persistent kernel: normalize -> grid barrier -> gram -> last-CTA lse.
// ---------------------------------------------------------------------------
#define SMEM_BYTES (2 * TILE * LDH * 2)    // As + Bs = 69632

__global__ __launch_bounds__(256, 3) void gram_mma_kernel(
    const float* __restrict__ in, float* __restrict__ out)
{
    extern __shared__ char smem[];
    __half* As = (__half*)smem;
    __half* Bs = As + TILE * LDH;

    const int tid  = threadIdx.x;
    const int wid  = tid >> 5;
    const int lane = tid & 31;
    const int wrow = wid >> 2;
    const int wcol = wid & 3;
    const int g    = lane >> 2;
    const int tg   = lane & 3;

    // ===== Phase 0: normalize (x sqrt(log2 e)) + zero accumulators =====
    for (int row = blockIdx.x * 8 + wid; row < N; row += NCTA * 8) {
        float4 v = ((const float4*)(in + (size_t)row * D))[lane];
        float ss = v.x * v.x + v.y * v.y + v.z * v.z + v.w * v.w;
#pragma unroll
        for (int o = 16; o > 0; o >>= 1) ss += __shfl_xor_sync(0xffffffffu, ss, o);
        float scale = SQRT_LOG2E / fmaxf(sqrtf(ss), 1e-12f);
        __half2 h0 = __floats2half2_rn(v.x * scale, v.y * scale);
        __half2 h1 = __floats2half2_rn(v.z * scale, v.w * scale);
        ((__half2*)(g_fh + (size_t)row * D))[lane * 2 + 0] = h0;
        ((__half2*)(g_fh + (size_t)row * D))[lane * 2 + 1] = h1;
    }
    for (int r = blockIdx.x * 256 + tid; r < N; r += NCTA * 256) {
        g_suffix[r] = 0.0f;
        g_prefix[r] = 0.0f;
    }

    // ===== Grid barrier (all 444 CTAs co-resident) =====
    if (tid == 0) {
        __threadfence();
        atomicAdd(&g_sync, 1u);
        unsigned v;
        do {
            asm volatile("ld.acquire.gpu.global.u32 %0, [%1];"
                         : "=r"(v) : "l"(&g_sync));
            if (v < NCTA) __nanosleep(32);
        } while (v < NCTA);
    }
    __syncthreads();

    // ===== Phase 1: persistent gram =====
    const uint32_t As_s = smem_u32(As);
    const uint32_t Bs_s = smem_u32(Bs);

    const uint32_t aoff  = (uint32_t)((lane & 15) * LDH + (lane >> 4) * 8) * 2u;
    // B x4 layout: lanes 0-7 -> nt rows, 8-15 -> +k8, 16-23 -> nt+1 rows, 24-31 -> nt+1,+k8
    const uint32_t boff4 = (uint32_t)((lane & 7) * LDH + ((lane >> 3) & 1) * 8 +
                                      ((lane >> 4) & 1) * 8 * LDH) * 2u;

    const int lo = (int)(((long long)blockIdx.x * NTRI) / NCTA);
    const int hi = (int)(((long long)(blockIdx.x + 1) * NTRI) / NCTA);

    int I = 0;
    while ((I + 1) * NB - (I + 1) * I / 2 <= lo) ++I;
    {
        const int J0 = I + (lo - (I * NB - I * (I - 1) / 2));
        prefetch_tile(As_s, g_fh + (size_t)I * TILE * D, tid);
        prefetch_tile(Bs_s, g_fh + (size_t)J0 * TILE * D, tid);
        CP_COMMIT();
    }

    for (int t = lo; t < hi; ++t) {
        while ((I + 1) * NB - (I + 1) * I / 2 <= t) ++I;
        const int J = I + (t - (I * NB - I * (I - 1) / 2));

        int In = I, Jn = 0;
        const bool have_next = (t + 1 < hi);
        if (have_next) {
            while ((In + 1) * NB - (In + 1) * In / 2 <= t + 1) ++In;
            Jn = In + ((t + 1) - (In * NB - In * (In - 1) / 2));
        }

        CP_WAIT_ALL();
        __syncthreads();

        const uint32_t Acur = As_s + aoff;
        const uint32_t Bcur = Bs_s + boff4;

        uint32_t acc[4][4][2];
#pragma unroll
        for (int mt = 0; mt < 4; mt++)
#pragma unroll
            for (int nt = 0; nt < 4; nt++) {
                acc[mt][nt][0] = 0u;
                acc[mt][nt][1] = 0u;
            }

#pragma unroll
        for (int k0 = 0; k0 < D; k0 += 16) {
            uint32_t bfr[4][2];
            uint32_t afr[4][4];
#pragma unroll
            for (int np = 0; np < 2; np++)      // two x4 loads cover 4 nt blocks
                ldsm_x4(bfr[np * 2][0], bfr[np * 2][1],
                        bfr[np * 2 + 1][0], bfr[np * 2 + 1][1],
                        Bcur + (uint32_t)((wcol * 32 + np * 16) * LDH + k0) * 2u);
#pragma unroll
            for (int mt = 0; mt < 4; mt++)
                ldsm_x4(afr[mt][0], afr[mt][1], afr[mt][2], afr[mt][3],
                        Acur + (uint32_t)((wrow * 64 + mt * 16) * LDH + k0) * 2u);
#pragma unroll
            for (int mt = 0; mt < 4; mt++)
#pragma unroll
                for (int nt = 0; nt < 4; nt++)
                    mma16816_h(acc[mt][nt], afr[mt][0], afr[mt][1],
                               afr[mt][2], afr[mt][3], bfr[nt][0], bfr[nt][1]);
        }

        __syncthreads();
        if (have_next) {
            prefetch_tile(Bs_s, g_fh + (size_t)Jn * TILE * D, tid);
            if (In != I)
                prefetch_tile(As_s, g_fh + (size_t)In * TILE * D, tid);
            CP_COMMIT();
        }

        // --- Epilogue ---
        if (J > I + 1) {
            __half2 csp[4];
#pragma unroll
            for (int nt = 0; nt < 4; nt++) csp[nt] = __floats2half2_rn(0.f, 0.f);

#pragma unroll
            for (int mt = 0; mt < 4; mt++) {
                __half2 rs0p = __floats2half2_rn(0.f, 0.f);
                __half2 rs1p = __floats2half2_rn(0.f, 0.f);
#pragma unroll
                for (int nt = 0; nt < 4; nt++) {
                    __half2 e0 = h2exp2(*(__half2*)&acc[mt][nt][0]);
                    __half2 e1 = h2exp2(*(__half2*)&acc[mt][nt][1]);
                    rs0p = __hadd2(rs0p, e0);
                    rs1p = __hadd2(rs1p, e1);
                    csp[nt] = __hadd2(csp[nt], __hadd2(e0, e1));
                }
                float rs0 = __low2float(rs0p) + __high2float(rs0p);
                float rs1 = __low2float(rs1p) + __high2float(rs1p);
                rs0 += __shfl_xor_sync(0xffffffffu, rs0, 1);
                rs0 += __shfl_xor_sync(0xffffffffu, rs0, 2);
                rs1 += __shfl_xor_sync(0xffffffffu, rs1, 1);
                rs1 += __shfl_xor_sync(0xffffffffu, rs1, 2);
                if (tg == 0) {
                    atomicAdd(&g_suffix[I * TILE + wrow * 64 + mt * 16 + g], rs0);
                    atomicAdd(&g_suffix[I * TILE + wrow * 64 + mt * 16 + g + 8], rs1);
                }
            }
            // packed half2 column reduce: shuffle the b32 as a unit
#pragma unroll
            for (int nt = 0; nt < 4; nt++) {
                uint32_t v = *(uint32_t*)&csp[nt];
#pragma unroll
                for (int o = 4; o <= 16; o <<= 1) {
                    uint32_t u = __shfl_xor_sync(0xffffffffu, v, o);
                    __half2 s = __hadd2(*(__half2*)&v, *(__half2*)&u);
                    v = *(uint32_t*)&s;
                }
                if (g == 0) {
                    __half2 s = *(__half2*)&v;
                    atomicAdd(&g_prefix[J * TILE + wcol * 32 + nt * 8 + tg * 2 + 0],
                              __low2float(s));
                    atomicAdd(&g_prefix[J * TILE + wcol * 32 + nt * 8 + tg * 2 + 1],
                              __high2float(s));
                }
            }
        } else {
            float csum[4][2];
#pragma unroll
            for (int nt = 0; nt < 4; nt++) { csum[nt][0] = 0.0f; csum[nt][1] = 0.0f; }
#pragma unroll
            for (int mt = 0; mt < 4; mt++) {
                const int gi0 = I * TILE + wrow * 64 + mt * 16 + g;
                const int gi1 = gi0 + 8;
                float rs0 = 0.0f, rs1 = 0.0f;
#pragma unroll
                for (int nt = 0; nt < 4; nt++) {
                    const int gj0 = J * TILE + wcol * 32 + nt * 8 + tg * 2;
                    const int gj1 = gj0 + 1;
                    float2 f0 = __half22float2(*(__half2*)&acc[mt][nt][0]);
                    float2 f1 = __half22float2(*(__half2*)&acc[mt][nt][1]);
                    float e00 = (gj0 > gi0) ? ex2f(f0.x) : 0.0f;
                    float e01 = (gj1 > gi0) ? ex2f(f0.y) : 0.0f;
                    float e10 = (gj0 > gi1) ? ex2f(f1.x) : 0.0f;
                    float e11 = (gj1 > gi1) ? ex2f(f1.y) : 0.0f;
                    rs0 += e00 + e01;
                    rs1 += e10 + e11;
                    csum[nt][0] += ((gj0 >= gi0 + 2) ? e00 : 0.0f) + ((gj0 >= gi1 + 2) ? e10 : 0.0f);
                    csum[nt][1] += ((gj1 >= gi0 + 2) ? e01 : 0.0f) + ((gj1 >= gi1 + 2) ? e11 : 0.0f);
                    if (gj0 == gi0 + 1) g_pos[gi0] = f0.x;
                    if (gj1 == gi0 + 1) g_pos[gi0] = f0.y;
                    if (gj0 == gi1 + 1) g_pos[gi1] = f1.x;
                    if (gj1 == gi1 + 1) g_pos[gi1] = f1.y;
                }
                rs0 += __shfl_xor_sync(0xffffffffu, rs0, 1);
                rs0 += __shfl_xor_sync(0xffffffffu, rs0, 2);
                rs1 += __shfl_xor_sync(0xffffffffu, rs1, 1);
                rs1 += __shfl_xor_sync(0xffffffffu, rs1, 2);
                if (tg == 0) {
                    atomicAdd(&g_suffix[gi0], rs0);
                    atomicAdd(&g_suffix[gi1], rs1);
                }
            }
#pragma unroll
            for (int nt = 0; nt < 4; nt++) {
#pragma unroll
                for (int e = 0; e < 2; e++) {
                    float v = csum[nt][e];
                    v += __shfl_xor_sync(0xffffffffu, v, 4);
                    v += __shfl_xor_sync(0xffffffffu, v, 8);
                    v += __shfl_xor_sync(0xffffffffu, v, 16);
                    if (g == 0)
                        atomicAdd(&g_prefix[J * TILE + wcol * 32 + nt * 8 + tg * 2 + e], v);
                }
            }
        }
    }

    // ===== Last-CTA finish =====
    __shared__ unsigned s_last;
    if (tid == 0) {
        __threadfence();
        s_last = (atomicAdd(&g_done, 1u) == NCTA - 1) ? 1u : 0u;
    }
    __syncthreads();
    if (!s_last) return;

    __threadfence();

    float* red = (float*)smem;
    float local = 0.0f;
    for (int r = tid; r < N - 1; r += 256)
        local += __logf(g_suffix[r] + g_prefix[r + 1]) - g_pos[r] * LN2;
#pragma unroll
    for (int o = 16; o > 0; o >>= 1)
        local += __shfl_xor_sync(0xffffffffu, local, o);
    if (lane == 0) red[wid] = local;
    __syncthreads();
    if (tid == 0) {
        float v = 0.0f;
#pragma unroll
        for (int w = 0; w < 8; w++) v += red[w];
        out[0] = -WEIGHT * (v / (float)N);
        g_sync = 0;                    // reset for next graph replay
        g_done = 0;
    }
}

// ---------------------------------------------------------------------------
extern "C" void kernel_launch(void* const* d_in, const int* in_sizes, int n_in,
                              void* d_out, int out_size) {
    const float* factor = (const float*)d_in[0];
    (void)in_sizes; (void)n_in; (void)out_size;

    static bool attr_set = false;
    if (!attr_set) {
        cudaFuncSetAttribute(gram_mma_kernel,
                             cudaFuncAttributeMaxDynamicSharedMemorySize, SMEM_BYTES);
        attr_set = true;
    }

    gram_mma_kernel<<<NCTA, 256, SMEM_BYTES>>>(factor, (float*)d_out);
}